// round 1
// baseline (speedup 1.0000x reference)
#include <cuda_runtime.h>
#include <math.h>

#define NB 64
#define NS 4096
#define CHUNKS 8
#define CHUNK 512
#define NTHREADS 256
#define EPT 2
#define NELEM (NB*NS)
#define EPSF 1e-6f
#define SB_STRIDE 13

struct Xf { float r[9]; float t[3]; };

// Scratch (device globals: allocation inside kernel_launch is forbidden)
__device__ float  g_poses[(size_t)NELEM * 24];   // per element: est Xf (12), gt Xf (12) -- SHIFTED poses
__device__ float  g_cprod[NB * CHUNKS * 24];     // chunk total products (est,gt)
__device__ float  g_cpre [NB * CHUNKS * 24];     // exclusive chunk prefixes (est,gt)
__device__ double g_accum[6];                    // sq_pos, ab_pos, odom_ang, sq_traj, ab_traj, traj_ang

__device__ __forceinline__ Xf xf_identity() {
    Xf x;
#pragma unroll
    for (int i = 0; i < 9; i++) x.r[i] = 0.f;
    x.r[0] = x.r[4] = x.r[8] = 1.f;
    x.t[0] = x.t[1] = x.t[2] = 0.f;
    return x;
}

// C = A @ B for rigid transforms: R = Ra*Rb, t = Ra*tb + ta
__device__ __forceinline__ Xf xf_compose(const Xf& A, const Xf& B) {
    Xf C;
#pragma unroll
    for (int i = 0; i < 3; i++) {
        float a0 = A.r[i*3+0], a1 = A.r[i*3+1], a2 = A.r[i*3+2];
#pragma unroll
        for (int j = 0; j < 3; j++)
            C.r[i*3+j] = fmaf(a0, B.r[j], fmaf(a1, B.r[3+j], a2 * B.r[6+j]));
        C.t[i] = fmaf(a0, B.t[0], fmaf(a1, B.t[1], fmaf(a2, B.t[2], A.t[i])));
    }
    return C;
}

__device__ __forceinline__ void euler_to_R(const float e[3], float r[9]) {
    float sa, ca, sb, cb, sc, cc;
    sincosf(e[0], &sa, &ca);
    sincosf(e[1], &sb, &cb);
    sincosf(e[2], &sc, &cc);
    r[0] = cc*cb; r[1] = cc*sb*sa - sc*ca; r[2] = cc*sb*ca + sc*sa;
    r[3] = sc*cb; r[4] = sc*sb*sa + cc*ca; r[5] = sc*sb*ca - cc*sa;
    r[6] = -sb;   r[7] = cb*sa;            r[8] = cb*ca;
}

__device__ __forceinline__ float rot_angle(const float* r1, const float* r2) {
    float tr = 0.f;
#pragma unroll
    for (int k = 0; k < 9; k++) tr = fmaf(r1[k], r2[k], tr);  // trace(R1 R2^T)
    float c = 0.5f * (tr - 1.f);
    c = fminf(fmaxf(c, -1.f + EPSF), 1.f - EPSF);
    return acosf(c);
}

// 12-float global load/store (offsets are multiples of 12 floats => 16B aligned)
__device__ __forceinline__ Xf xf_load_g(const float* p) {
    Xf x;
    float4 a = *(const float4*)(p), b = *(const float4*)(p + 4), c = *(const float4*)(p + 8);
    x.r[0]=a.x; x.r[1]=a.y; x.r[2]=a.z; x.r[3]=a.w;
    x.r[4]=b.x; x.r[5]=b.y; x.r[6]=b.z; x.r[7]=b.w;
    x.r[8]=c.x; x.t[0]=c.y; x.t[1]=c.z; x.t[2]=c.w;
    return x;
}
__device__ __forceinline__ void xf_store_g(float* p, const Xf& x) {
    *(float4*)(p)     = make_float4(x.r[0], x.r[1], x.r[2], x.r[3]);
    *(float4*)(p + 4) = make_float4(x.r[4], x.r[5], x.r[6], x.r[7]);
    *(float4*)(p + 8) = make_float4(x.r[8], x.t[0], x.t[1], x.t[2]);
}

__device__ __forceinline__ void xf_store_s(float* sb, int i, const Xf& x) {
    float* p = sb + i * SB_STRIDE;
#pragma unroll
    for (int k = 0; k < 9; k++) p[k] = x.r[k];
    p[9] = x.t[0]; p[10] = x.t[1]; p[11] = x.t[2];
}
__device__ __forceinline__ Xf xf_load_s(const float* sb, int i) {
    const float* p = sb + i * SB_STRIDE;
    Xf x;
#pragma unroll
    for (int k = 0; k < 9; k++) x.r[k] = p[k];
    x.t[0] = p[9]; x.t[1] = p[10]; x.t[2] = p[11];
    return x;
}

// Hillis-Steele inclusive scan over 256 thread-products (order-preserving left compose).
// On return: register = inclusive[tid], sb holds inclusive values.
__device__ __forceinline__ Xf block_scan(Xf mine, float* sb) {
    int tid = threadIdx.x;
    xf_store_s(sb, tid, mine);
    __syncthreads();
#pragma unroll
    for (int off = 1; off < NTHREADS; off <<= 1) {
        Xf left;
        bool h = (tid >= off);
        if (h) left = xf_load_s(sb, tid - off);
        __syncthreads();
        if (h) { mine = xf_compose(left, mine); xf_store_s(sb, tid, mine); }
        __syncthreads();
    }
    return mine;
}

__device__ __forceinline__ void block_reduce_atomic3(float v0, float v1, float v2, int base) {
#pragma unroll
    for (int o = 16; o > 0; o >>= 1) {
        v0 += __shfl_down_sync(0xffffffffu, v0, o);
        v1 += __shfl_down_sync(0xffffffffu, v1, o);
        v2 += __shfl_down_sync(0xffffffffu, v2, o);
    }
    __shared__ double w[3][NTHREADS / 32];
    int lane = threadIdx.x & 31, wid = threadIdx.x >> 5;
    if (lane == 0) { w[0][wid] = v0; w[1][wid] = v1; w[2][wid] = v2; }
    __syncthreads();
    if (threadIdx.x < 3) {
        double s = 0.0;
#pragma unroll
        for (int i = 0; i < NTHREADS / 32; i++) s += w[threadIdx.x][i];
        atomicAdd(&g_accum[base + threadIdx.x], s);
    }
}

__global__ void k_zero() { if (threadIdx.x < 6) g_accum[threadIdx.x] = 0.0; }

// Phase 1: build poses, odometry pointwise losses, chunk total products.
__global__ void __launch_bounds__(NTHREADS) k_phase1(
    const float* __restrict__ yhat, const float* __restrict__ gpos,
    const float* __restrict__ gori) {
    __shared__ float sb[NTHREADS * SB_STRIDE];
    int tid = threadIdx.x;
    int chunk = blockIdx.x, batch = blockIdx.y;
    int s0 = chunk * CHUNK + tid * EPT;
    int idx0 = batch * NS + s0;

    float4 y0 = *(const float4*)(yhat + idx0 * 6);
    float4 y1 = *(const float4*)(yhat + idx0 * 6 + 4);
    float4 y2 = *(const float4*)(yhat + idx0 * 6 + 8);
    float2 p0 = *(const float2*)(gpos + idx0 * 3);
    float2 p1 = *(const float2*)(gpos + idx0 * 3 + 2);
    float2 p2 = *(const float2*)(gpos + idx0 * 3 + 4);
    float2 o0 = *(const float2*)(gori + idx0 * 3);
    float2 o1 = *(const float2*)(gori + idx0 * 3 + 2);
    float2 o2 = *(const float2*)(gori + idx0 * 3 + 4);

    float eo[2][3] = {{y0.x, y0.y, y0.z}, {y1.z, y1.w, y2.x}};  // pred orientations
    float ep[2][3] = {{y0.w, y1.x, y1.y}, {y2.y, y2.z, y2.w}};  // pred positions
    float go[2][3] = {{o0.x, o0.y, o1.x}, {o1.y, o2.x, o2.y}};  // gt orientations
    float gp[2][3] = {{p0.x, p0.y, p1.x}, {p1.y, p2.x, p2.y}};  // gt positions

    float a_sq = 0.f, a_ab = 0.f, a_ang = 0.f;
    Xf spE[2], spG[2];
#pragma unroll
    for (int i = 0; i < 2; i++) {
        Xf pe, pg;
        euler_to_R(eo[i], pe.r);
        pe.t[0] = ep[i][0]; pe.t[1] = ep[i][1]; pe.t[2] = ep[i][2];
        euler_to_R(go[i], pg.r);
        pg.t[0] = gp[i][0]; pg.t[1] = gp[i][1]; pg.t[2] = gp[i][2];
#pragma unroll
        for (int k = 0; k < 3; k++) {
            float d = ep[i][k] - gp[i][k];
            a_sq = fmaf(d, d, a_sq);
            a_ab += fabsf(d);
        }
        a_ang += rot_angle(pe.r, pg.r);
        if (s0 + i == 0) { pe = xf_identity(); pg = xf_identity(); }  // shifted[...,0] = I
        float* gpp = g_poses + (size_t)(idx0 + i) * 24;
        xf_store_g(gpp, pe);
        xf_store_g(gpp + 12, pg);
        spE[i] = pe; spG[i] = pg;
    }

    Xf incE = block_scan(xf_compose(spE[0], spE[1]), sb);
    if (tid == NTHREADS - 1) xf_store_g(g_cprod + (batch * CHUNKS + chunk) * 24, incE);
    __syncthreads();
    Xf incG = block_scan(xf_compose(spG[0], spG[1]), sb);
    if (tid == NTHREADS - 1) xf_store_g(g_cprod + (batch * CHUNKS + chunk) * 24 + 12, incG);
    __syncthreads();

    block_reduce_atomic3(a_sq, a_ab, a_ang, 0);
}

// Phase 2: per-batch exclusive scan over the 8 chunk products.
__global__ void k_phase2() {
    int b = threadIdx.x;
    if (b >= NB) return;
    Xf aE = xf_identity(), aG = xf_identity();
    for (int c = 0; c < CHUNKS; c++) {
        float* pre = g_cpre + (b * CHUNKS + c) * 24;
        xf_store_g(pre, aE);
        xf_store_g(pre + 12, aG);
        const float* pr = g_cprod + (b * CHUNKS + c) * 24;
        aE = xf_compose(aE, xf_load_g(pr));
        aG = xf_compose(aG, xf_load_g(pr + 12));
    }
}

// Phase 3: apply prefixes, compute trajectory losses.
__global__ void __launch_bounds__(NTHREADS) k_phase3() {
    __shared__ float sb[NTHREADS * SB_STRIDE];
    int tid = threadIdx.x;
    int chunk = blockIdx.x, batch = blockIdx.y;
    int s0 = chunk * CHUNK + tid * EPT;
    int idx0 = batch * NS + s0;

    const float* pp = g_poses + (size_t)idx0 * 24;
    Xf p0e = xf_load_g(pp),      p0g = xf_load_g(pp + 12);
    Xf p1e = xf_load_g(pp + 24), p1g = xf_load_g(pp + 36);

    (void)block_scan(xf_compose(p0e, p1e), sb);
    Xf excE = (tid > 0) ? xf_load_s(sb, tid - 1) : xf_identity();
    __syncthreads();
    (void)block_scan(xf_compose(p0g, p1g), sb);
    Xf excG = (tid > 0) ? xf_load_s(sb, tid - 1) : xf_identity();
    __syncthreads();

    const float* cp = g_cpre + (batch * CHUNKS + chunk) * 24;
    Xf preE = xf_compose(xf_load_g(cp), excE);
    Xf preG = xf_compose(xf_load_g(cp + 12), excG);

    float t_sq = 0.f, t_ab = 0.f, t_ang = 0.f;
    Xf cE = xf_compose(preE, p0e);
    Xf cG = xf_compose(preG, p0g);
#pragma unroll
    for (int i = 0; i < 2; i++) {
        if (i == 1) { cE = xf_compose(cE, p1e); cG = xf_compose(cG, p1g); }
#pragma unroll
        for (int k = 0; k < 3; k++) {
            float d = cE.t[k] - cG.t[k];
            t_sq = fmaf(d, d, t_sq);
            t_ab += fabsf(d);
        }
        t_ang += rot_angle(cE.r, cG.r);
    }
    block_reduce_atomic3(t_sq, t_ab, t_ang, 3);
}

__global__ void k_final(float* out) {
    const double n3 = (double)NELEM * 3.0, n1 = (double)NELEM;
    double mse_pos = g_accum[0] / n3, mae_pos = g_accum[1] / n3, odom_rot = g_accum[2] / n1;
    double tmse = g_accum[3] / n3,    tmae = g_accum[4] / n3,    trot = g_accum[5] / n1;
    double odom = odom_rot + (mse_pos + mae_pos);
    double traj = trot + (tmse + tmae);
    out[0] = (float)(0.5 * odom + 0.5 * traj);
}

extern "C" void kernel_launch(void* const* d_in, const int* in_sizes, int n_in,
                              void* d_out, int out_size) {
    const float* yhat = (const float*)d_in[0];
    const float* gpos = (const float*)d_in[1];
    const float* gori = (const float*)d_in[2];
    k_zero<<<1, 32>>>();
    k_phase1<<<dim3(CHUNKS, NB), NTHREADS>>>(yhat, gpos, gori);
    k_phase2<<<1, 64>>>();
    k_phase3<<<dim3(CHUNKS, NB), NTHREADS>>>();
    k_final<<<1, 1>>>((float*)d_out);
}

// round 2
// speedup vs baseline: 1.1140x; 1.1140x over previous
#include <cuda_runtime.h>
#include <math.h>

#define NB 64
#define NS 4096
#define CHUNKS 16
#define CHUNK 256
#define NTHREADS 256
#define NWARPS (NTHREADS / 32)
#define NELEM (NB * NS)
#define EPSF 1e-6f
#define FULLMASK 0xffffffffu

struct Xf { float v[12]; };  // v[0..8] = R row-major, v[9..11] = t

__device__ float  g_cprod[NB * CHUNKS * 24];   // chunk total products (est,gt)
__device__ float  g_cpre [NB * CHUNKS * 24];   // exclusive chunk prefixes (est,gt)
__device__ double g_accum[6];                  // sq_pos, ab_pos, odom_ang, sq_traj, ab_traj, traj_ang

__device__ __forceinline__ Xf xf_identity() {
    Xf x;
#pragma unroll
    for (int i = 0; i < 12; i++) x.v[i] = 0.f;
    x.v[0] = x.v[4] = x.v[8] = 1.f;
    return x;
}

// C = A @ B for rigid transforms
__device__ __forceinline__ Xf xf_compose(const Xf& A, const Xf& B) {
    Xf C;
#pragma unroll
    for (int i = 0; i < 3; i++) {
        float a0 = A.v[i*3+0], a1 = A.v[i*3+1], a2 = A.v[i*3+2];
#pragma unroll
        for (int j = 0; j < 3; j++)
            C.v[i*3+j] = fmaf(a0, B.v[j], fmaf(a1, B.v[3+j], a2 * B.v[6+j]));
        C.v[9+i] = fmaf(a0, B.v[9], fmaf(a1, B.v[10], fmaf(a2, B.v[11], A.v[9+i])));
    }
    return C;
}

__device__ __forceinline__ Xf xf_shfl_up(const Xf& x, int off) {
    Xf y;
#pragma unroll
    for (int k = 0; k < 12; k++) y.v[k] = __shfl_up_sync(FULLMASK, x.v[k], off);
    return y;
}

__device__ __forceinline__ void euler_to_R(float a, float b, float c, float* r) {
    float sa, ca, sb, cb, sc, cc;
    sincosf(a, &sa, &ca);
    sincosf(b, &sb, &cb);
    sincosf(c, &sc, &cc);
    r[0] = cc*cb; r[1] = cc*sb*sa - sc*ca; r[2] = cc*sb*ca + sc*sa;
    r[3] = sc*cb; r[4] = sc*sb*sa + cc*ca; r[5] = sc*sb*ca - cc*sa;
    r[6] = -sb;   r[7] = cb*sa;            r[8] = cb*ca;
}

__device__ __forceinline__ float rot_angle(const Xf& A, const Xf& B) {
    float tr = 0.f;
#pragma unroll
    for (int k = 0; k < 9; k++) tr = fmaf(A.v[k], B.v[k], tr);  // trace(Ra Rb^T)
    float c = 0.5f * (tr - 1.f);
    c = fminf(fmaxf(c, -1.f + EPSF), 1.f - EPSF);
    return acosf(c);
}

// 12-float aligned global load/store (offsets are multiples of 12 floats -> 16B aligned)
__device__ __forceinline__ Xf xf_load_g(const float* p) {
    Xf x;
    float4 a = *(const float4*)(p), b = *(const float4*)(p + 4), c = *(const float4*)(p + 8);
    x.v[0]=a.x; x.v[1]=a.y; x.v[2]=a.z; x.v[3]=a.w;
    x.v[4]=b.x; x.v[5]=b.y; x.v[6]=b.z; x.v[7]=b.w;
    x.v[8]=c.x; x.v[9]=c.y; x.v[10]=c.z; x.v[11]=c.w;
    return x;
}
__device__ __forceinline__ void xf_store_g(float* p, const Xf& x) {
    *(float4*)(p)     = make_float4(x.v[0], x.v[1], x.v[2],  x.v[3]);
    *(float4*)(p + 4) = make_float4(x.v[4], x.v[5], x.v[6],  x.v[7]);
    *(float4*)(p + 8) = make_float4(x.v[8], x.v[9], x.v[10], x.v[11]);
}

__device__ __forceinline__ void xf_store_s(float* p, const Xf& x) {
#pragma unroll
    for (int k = 0; k < 12; k++) p[k] = x.v[k];
}
__device__ __forceinline__ Xf xf_load_s(const float* p) {
    Xf x;
#pragma unroll
    for (int k = 0; k < 12; k++) x.v[k] = p[k];
    return x;
}

// Warp-level inclusive scan (order-preserving left compose) of the (E, G) pair.
__device__ __forceinline__ void warp_scan2(Xf& e, Xf& g, int lane) {
#pragma unroll
    for (int off = 1; off < 32; off <<= 1) {
        Xf le = xf_shfl_up(e, off);
        Xf lg = xf_shfl_up(g, off);
        if (lane >= off) { e = xf_compose(le, e); g = xf_compose(lg, g); }
    }
}

// Build the (shifted) est/gt poses for sequence index s; accumulate odom pointwise terms.
__device__ __forceinline__ void build_poses(
    const float* __restrict__ yhat, const float* __restrict__ gpos,
    const float* __restrict__ gori, int idx, int s,
    Xf& E, Xf& G, float& o_sq, float& o_ab, float& o_ang) {
    const float* y  = yhat + (size_t)idx * 6;
    const float* gp = gpos + (size_t)idx * 3;
    const float* go = gori + (size_t)idx * 3;
    euler_to_R(y[0], y[1], y[2], E.v);
    E.v[9] = y[3]; E.v[10] = y[4]; E.v[11] = y[5];
    euler_to_R(go[0], go[1], go[2], G.v);
    G.v[9] = gp[0]; G.v[10] = gp[1]; G.v[11] = gp[2];
    o_sq = 0.f; o_ab = 0.f;
#pragma unroll
    for (int k = 0; k < 3; k++) {
        float d = E.v[9+k] - G.v[9+k];
        o_sq = fmaf(d, d, o_sq);
        o_ab += fabsf(d);
    }
    o_ang = rot_angle(E, G);
    if (s == 0) { E = xf_identity(); G = xf_identity(); }  // shifted[...,0] = I
}

__device__ __forceinline__ void block_reduce6_atomic(float v[6]) {
#pragma unroll
    for (int o = 16; o > 0; o >>= 1)
#pragma unroll
        for (int j = 0; j < 6; j++) v[j] += __shfl_down_sync(FULLMASK, v[j], o);
    __shared__ float w[6][NWARPS];
    int lane = threadIdx.x & 31, wid = threadIdx.x >> 5;
    if (lane == 0)
#pragma unroll
        for (int j = 0; j < 6; j++) w[j][wid] = v[j];
    __syncthreads();
    if (threadIdx.x < 6) {
        double s = 0.0;
#pragma unroll
        for (int i = 0; i < NWARPS; i++) s += (double)w[threadIdx.x][i];
        atomicAdd(&g_accum[threadIdx.x], s);
    }
}

// Kernel 1: chunk total products (trig + warp scan + cross-warp serial compose).
__global__ void __launch_bounds__(NTHREADS) k_totals(
    const float* __restrict__ yhat, const float* __restrict__ gpos,
    const float* __restrict__ gori) {
    __shared__ float sw[2][NWARPS][12];
    int tid = threadIdx.x, lane = tid & 31, wid = tid >> 5;
    int chunk = blockIdx.x, batch = blockIdx.y;
    int s = chunk * CHUNK + tid;
    int idx = batch * NS + s;

    Xf E, G; float d0, d1, d2;
    build_poses(yhat, gpos, gori, idx, s, E, G, d0, d1, d2);
    warp_scan2(E, G, lane);
    if (lane == 31) { xf_store_s(sw[0][wid], E); xf_store_s(sw[1][wid], G); }
    __syncthreads();
    if (tid == 0) {
        Xf aE = xf_load_s(sw[0][0]);
        Xf aG = xf_load_s(sw[1][0]);
#pragma unroll
        for (int w = 1; w < NWARPS; w++) {
            aE = xf_compose(aE, xf_load_s(sw[0][w]));
            aG = xf_compose(aG, xf_load_s(sw[1][w]));
        }
        float* o = g_cprod + (batch * CHUNKS + chunk) * 24;
        xf_store_g(o, aE);
        xf_store_g(o + 12, aG);
    }
}

// Kernel 2: per-batch exclusive scan over the 16 chunk totals; zero accumulators.
__global__ void k_prefix() {
    int b = threadIdx.x;
    if (b < 6) g_accum[b] = 0.0;
    if (b >= NB) return;
    Xf aE = xf_identity(), aG = xf_identity();
    for (int c = 0; c < CHUNKS; c++) {
        float* pre = g_cpre + (b * CHUNKS + c) * 24;
        xf_store_g(pre, aE);
        xf_store_g(pre + 12, aG);
        const float* pr = g_cprod + (b * CHUNKS + c) * 24;
        aE = xf_compose(aE, xf_load_g(pr));
        aG = xf_compose(aG, xf_load_g(pr + 12));
    }
}

// Kernel 3: full scan (warp shuffle + cross-warp + chunk prefix) + all loss terms.
__global__ void __launch_bounds__(NTHREADS) k_scan_loss(
    const float* __restrict__ yhat, const float* __restrict__ gpos,
    const float* __restrict__ gori) {
    __shared__ float sw[2][NWARPS][12];
    int tid = threadIdx.x, lane = tid & 31, wid = tid >> 5;
    int chunk = blockIdx.x, batch = blockIdx.y;
    int s = chunk * CHUNK + tid;
    int idx = batch * NS + s;

    Xf E, G;
    float acc[6];
    build_poses(yhat, gpos, gori, idx, s, E, G, acc[0], acc[1], acc[2]);

    // Block-wide inclusive scan
    warp_scan2(E, G, lane);
    if (lane == 31) { xf_store_s(sw[0][wid], E); xf_store_s(sw[1][wid], G); }
    __syncthreads();
    if (wid == 0) {
        Xf te = (lane < NWARPS) ? xf_load_s(sw[0][lane]) : xf_identity();
        Xf tg = (lane < NWARPS) ? xf_load_s(sw[1][lane]) : xf_identity();
#pragma unroll
        for (int off = 1; off < NWARPS; off <<= 1) {
            Xf le = xf_shfl_up(te, off);
            Xf lg = xf_shfl_up(tg, off);
            if (lane >= off && lane < NWARPS) { te = xf_compose(le, te); tg = xf_compose(lg, tg); }
        }
        if (lane < NWARPS) { xf_store_s(sw[0][lane], te); xf_store_s(sw[1][lane], tg); }
    }
    __syncthreads();
    if (wid > 0) {
        E = xf_compose(xf_load_s(sw[0][wid-1]), E);
        G = xf_compose(xf_load_s(sw[1][wid-1]), G);
    }
    // Apply chunk-level exclusive prefix
    const float* cp = g_cpre + (batch * CHUNKS + chunk) * 24;
    E = xf_compose(xf_load_g(cp), E);
    G = xf_compose(xf_load_g(cp + 12), G);

    // Trajectory loss terms
    acc[3] = 0.f; acc[4] = 0.f;
#pragma unroll
    for (int k = 0; k < 3; k++) {
        float d = E.v[9+k] - G.v[9+k];
        acc[3] = fmaf(d, d, acc[3]);
        acc[4] += fabsf(d);
    }
    acc[5] = rot_angle(E, G);
    block_reduce6_atomic(acc);
}

__global__ void k_final(float* out) {
    const double n3 = (double)NELEM * 3.0, n1 = (double)NELEM;
    double odom = g_accum[2] / n1 + (g_accum[0] / n3 + g_accum[1] / n3);
    double traj = g_accum[5] / n1 + (g_accum[3] / n3 + g_accum[4] / n3);
    out[0] = (float)(0.5 * odom + 0.5 * traj);
}

extern "C" void kernel_launch(void* const* d_in, const int* in_sizes, int n_in,
                              void* d_out, int out_size) {
    const float* yhat = (const float*)d_in[0];
    const float* gpos = (const float*)d_in[1];
    const float* gori = (const float*)d_in[2];
    k_totals<<<dim3(CHUNKS, NB), NTHREADS>>>(yhat, gpos, gori);
    k_prefix<<<1, 64>>>();
    k_scan_loss<<<dim3(CHUNKS, NB), NTHREADS>>>(yhat, gpos, gori);
    k_final<<<1, 1>>>((float*)d_out);
}

// round 4
// speedup vs baseline: 1.4091x; 1.2649x over previous
#include <cuda_runtime.h>
#include <math.h>

#define NB 64
#define NS 4096
#define CHUNKS 16
#define CHUNK 256
#define NTHREADS 256
#define NWARPS 8
#define NBLOCKS (NB * CHUNKS)
#define NELEM (NB * NS)
#define EPSF 1e-6f
#define FULLMASK 0xffffffffu

// Pose = quaternion (w,x,y,z) + translation. 7 floats (vs 12 for 3x4 matrix).
struct Pose { float qw, qx, qy, qz, tx, ty, tz; };

__device__ float  g_agg[NBLOCKS][16];   // chunk aggregate   (E in [0..6], G in [8..14])
__device__ float  g_pre[NBLOCKS][16];   // chunk inclusive prefix
__device__ int    g_flag[NBLOCKS];      // 0=none, 1=aggregate ready, 2=prefix ready
__device__ double g_accum[6];           // sq_pos, ab_pos, odom_ang, sq_traj, ab_traj, traj_ang

__device__ __forceinline__ Pose pidentity() { return Pose{1.f, 0.f, 0.f, 0.f, 0.f, 0.f, 0.f}; }

// C = A then B (matches einsum x@y order): q = qa*qb, t = ta + rot(qa, tb)
__device__ __forceinline__ Pose pcompose(const Pose& A, const Pose& B) {
    Pose C;
    C.qw = A.qw*B.qw - A.qx*B.qx - A.qy*B.qy - A.qz*B.qz;
    C.qx = A.qw*B.qx + A.qx*B.qw + A.qy*B.qz - A.qz*B.qy;
    C.qy = A.qw*B.qy - A.qx*B.qz + A.qy*B.qw + A.qz*B.qx;
    C.qz = A.qw*B.qz + A.qx*B.qy - A.qy*B.qx + A.qz*B.qw;
    // v' = v + qw*t2 + u x t2, t2 = 2 u x v
    float t2x = 2.f * (A.qy*B.tz - A.qz*B.ty);
    float t2y = 2.f * (A.qz*B.tx - A.qx*B.tz);
    float t2z = 2.f * (A.qx*B.ty - A.qy*B.tx);
    C.tx = A.tx + B.tx + A.qw*t2x + (A.qy*t2z - A.qz*t2y);
    C.ty = A.ty + B.ty + A.qw*t2y + (A.qz*t2x - A.qx*t2z);
    C.tz = A.tz + B.tz + A.qw*t2z + (A.qx*t2y - A.qy*t2x);
    return C;
}

__device__ __forceinline__ Pose pshfl_up(const Pose& p, int off) {
    Pose r;
    r.qw = __shfl_up_sync(FULLMASK, p.qw, off);
    r.qx = __shfl_up_sync(FULLMASK, p.qx, off);
    r.qy = __shfl_up_sync(FULLMASK, p.qy, off);
    r.qz = __shfl_up_sync(FULLMASK, p.qz, off);
    r.tx = __shfl_up_sync(FULLMASK, p.tx, off);
    r.ty = __shfl_up_sync(FULLMASK, p.ty, off);
    r.tz = __shfl_up_sync(FULLMASK, p.tz, off);
    return r;
}

// Quaternion for R = Rz(c) @ Ry(b) @ Rx(a)  (matches reference euler_xyz_to_mat)
// Accurate sincosf: __sincosf caused rel_err 1.12e-3 (R3 fail) via acos amplification.
__device__ __forceinline__ void euler_to_quat(float a, float b, float c, Pose& P) {
    float sa, ca, sb, cb, sc, cc;
    sincosf(0.5f * a, &sa, &ca);
    sincosf(0.5f * b, &sb, &cb);
    sincosf(0.5f * c, &sc, &cc);
    P.qw = cc*cb*ca + sc*sb*sa;
    P.qx = cc*cb*sa - sc*sb*ca;
    P.qy = cc*sb*ca + sc*cb*sa;
    P.qz = sc*cb*ca - cc*sb*sa;
}

// arccos((trace(R1 R2^T)-1)/2). For (possibly non-unit) quats:
// cos = 2*dot(q1,q2)^2/(|q1|^2 |q2|^2) - 1  -- norm drift cancels exactly.
__device__ __forceinline__ float rot_angle(const Pose& A, const Pose& B) {
    float d  = A.qw*B.qw + A.qx*B.qx + A.qy*B.qy + A.qz*B.qz;
    float n1 = A.qw*A.qw + A.qx*A.qx + A.qy*A.qy + A.qz*A.qz;
    float n2 = B.qw*B.qw + B.qx*B.qx + B.qy*B.qy + B.qz*B.qz;
    float c = 2.f * d * d / (n1 * n2) - 1.f;
    c = fminf(fmaxf(c, -1.f + EPSF), 1.f - EPSF);
    return acosf(c);
}

__device__ __forceinline__ void pstore_s(float* p, const Pose& x) {
    p[0]=x.qw; p[1]=x.qx; p[2]=x.qy; p[3]=x.qz; p[4]=x.tx; p[5]=x.ty; p[6]=x.tz;
}
__device__ __forceinline__ Pose pload_s(const float* p) {
    Pose x;
    x.qw=p[0]; x.qx=p[1]; x.qy=p[2]; x.qz=p[3]; x.tx=p[4]; x.ty=p[5]; x.tz=p[6];
    return x;
}
__device__ __forceinline__ void pair_store_g(float* p, const Pose& e, const Pose& g) {
    *(float4*)(p)      = make_float4(e.qw, e.qx, e.qy, e.qz);
    *(float4*)(p + 4)  = make_float4(e.tx, e.ty, e.tz, 0.f);
    *(float4*)(p + 8)  = make_float4(g.qw, g.qx, g.qy, g.qz);
    *(float4*)(p + 12) = make_float4(g.tx, g.ty, g.tz, 0.f);
}
__device__ __forceinline__ void pair_load_g(const float* p, Pose& e, Pose& g) {
    float4 a = *(const float4*)(p),     b = *(const float4*)(p + 4);
    float4 c = *(const float4*)(p + 8), d = *(const float4*)(p + 12);
    e.qw=a.x; e.qx=a.y; e.qy=a.z; e.qz=a.w; e.tx=b.x; e.ty=b.y; e.tz=b.z;
    g.qw=c.x; g.qx=c.y; g.qy=c.z; g.qz=c.w; g.tx=d.x; g.ty=d.y; g.tz=d.z;
}

__device__ __forceinline__ void block_reduce6_atomic(float v[6]) {
#pragma unroll
    for (int o = 16; o > 0; o >>= 1)
#pragma unroll
        for (int j = 0; j < 6; j++) v[j] += __shfl_down_sync(FULLMASK, v[j], o);
    __shared__ float w[6][NWARPS];
    int lane = threadIdx.x & 31, wid = threadIdx.x >> 5;
    if (lane == 0)
#pragma unroll
        for (int j = 0; j < 6; j++) w[j][wid] = v[j];
    __syncthreads();
    if (threadIdx.x < 6) {
        double s = 0.0;
#pragma unroll
        for (int i = 0; i < NWARPS; i++) s += (double)w[threadIdx.x][i];
        atomicAdd(&g_accum[threadIdx.x], s);
    }
}

__global__ void k_init() {
    int i = blockIdx.x * blockDim.x + threadIdx.x;
    if (i < NBLOCKS) g_flag[i] = 0;
    if (i < 6) g_accum[i] = 0.0;
}

// Single-pass fused kernel: pose build + block scan + decoupled lookback + all losses.
__global__ void __launch_bounds__(NTHREADS) k_main(
    const float* __restrict__ yhat, const float* __restrict__ gpos,
    const float* __restrict__ gori) {
    __shared__ float sw[2][NWARPS][8];
    __shared__ float sexc[2][8];
    int tid = threadIdx.x, lane = tid & 31, wid = tid >> 5;
    int bid = blockIdx.x;
    int batch = bid >> 4, chunk = bid & (CHUNKS - 1);
    int s = chunk * CHUNK + tid;
    int idx = batch * NS + s;

    // ---- build poses + odometry pointwise terms ----
    const float* y  = yhat + (size_t)idx * 6;
    const float* gp = gpos + (size_t)idx * 3;
    const float* go = gori + (size_t)idx * 3;
    Pose E, G;
    euler_to_quat(y[0], y[1], y[2], E);
    E.tx = y[3]; E.ty = y[4]; E.tz = y[5];
    euler_to_quat(go[0], go[1], go[2], G);
    G.tx = gp[0]; G.ty = gp[1]; G.tz = gp[2];

    float acc[6];
    acc[0] = 0.f; acc[1] = 0.f;
#pragma unroll
    for (int k = 0; k < 3; k++) {
        float d = (&E.tx)[k] - (&G.tx)[k];
        acc[0] = fmaf(d, d, acc[0]);
        acc[1] += fabsf(d);
    }
    acc[2] = rot_angle(E, G);
    if (s == 0) { E = pidentity(); G = pidentity(); }  // shifted[...,0] = I

    // ---- warp-level inclusive scan (left compose) ----
#pragma unroll
    for (int off = 1; off < 32; off <<= 1) {
        Pose le = pshfl_up(E, off), lg = pshfl_up(G, off);
        if (lane >= off) { E = pcompose(le, E); G = pcompose(lg, G); }
    }
    if (lane == 31) { pstore_s(sw[0][wid], E); pstore_s(sw[1][wid], G); }
    __syncthreads();

    // ---- cross-warp scan (warp 0) ----
    if (wid == 0) {
        Pose te = (lane < NWARPS) ? pload_s(sw[0][lane]) : pidentity();
        Pose tg = (lane < NWARPS) ? pload_s(sw[1][lane]) : pidentity();
#pragma unroll
        for (int off = 1; off < NWARPS; off <<= 1) {
            Pose le = pshfl_up(te, off), lg = pshfl_up(tg, off);
            if (lane >= off && lane < NWARPS) { te = pcompose(le, te); tg = pcompose(lg, tg); }
        }
        if (lane < NWARPS) { pstore_s(sw[0][lane], te); pstore_s(sw[1][lane], tg); }
    }
    __syncthreads();

    // ---- thread 0: publish aggregate, lookback, publish prefix ----
    if (tid == 0) {
        Pose aE = pload_s(sw[0][NWARPS - 1]);
        Pose aG = pload_s(sw[1][NWARPS - 1]);
        if (chunk < CHUNKS - 1) {
            pair_store_g(g_agg[bid], aE, aG);
            __threadfence();
            atomicExch(&g_flag[bid], 1);
        }
        Pose excE = pidentity(), excG = pidentity();
        if (chunk > 0) {
            Pose accE = pidentity(), accG = pidentity();
            bool have = false;
            int base = batch * CHUNKS;
            for (int i = bid - 1; i >= base; --i) {
                int f;
                volatile int* vf = g_flag;
                while ((f = vf[i]) == 0) { __nanosleep(32); }
                __threadfence();
                Pose pE, pG;
                if (f == 2) {
                    pair_load_g(g_pre[i], pE, pG);
                    excE = pcompose(pE, accE);
                    excG = pcompose(pG, accG);
                    have = true;
                    break;
                } else {
                    pair_load_g(g_agg[i], pE, pG);
                    accE = pcompose(pE, accE);
                    accG = pcompose(pG, accG);
                }
            }
            if (!have) { excE = accE; excG = accG; }
        }
        if (chunk < CHUNKS - 1) {
            Pose pE = pcompose(excE, aE), pG = pcompose(excG, aG);
            pair_store_g(g_pre[bid], pE, pG);
            __threadfence();
            atomicExch(&g_flag[bid], 2);
        }
        pstore_s(sexc[0], excE);
        pstore_s(sexc[1], excG);
    }
    __syncthreads();

    // ---- apply prefixes, trajectory losses ----
    Pose preE = pload_s(sexc[0]);
    Pose preG = pload_s(sexc[1]);
    if (wid > 0) {
        preE = pcompose(preE, pload_s(sw[0][wid - 1]));
        preG = pcompose(preG, pload_s(sw[1][wid - 1]));
    }
    Pose CE = pcompose(preE, E);
    Pose CG = pcompose(preG, G);

    acc[3] = 0.f; acc[4] = 0.f;
#pragma unroll
    for (int k = 0; k < 3; k++) {
        float d = (&CE.tx)[k] - (&CG.tx)[k];
        acc[3] = fmaf(d, d, acc[3]);
        acc[4] += fabsf(d);
    }
    acc[5] = rot_angle(CE, CG);
    block_reduce6_atomic(acc);
}

__global__ void k_final(float* out) {
    const double n3 = (double)NELEM * 3.0, n1 = (double)NELEM;
    double odom = g_accum[2] / n1 + (g_accum[0] / n3 + g_accum[1] / n3);
    double traj = g_accum[5] / n1 + (g_accum[3] / n3 + g_accum[4] / n3);
    out[0] = (float)(0.5 * odom + 0.5 * traj);
}

extern "C" void kernel_launch(void* const* d_in, const int* in_sizes, int n_in,
                              void* d_out, int out_size) {
    const float* yhat = (const float*)d_in[0];
    const float* gpos = (const float*)d_in[1];
    const float* gori = (const float*)d_in[2];
    k_init<<<(NBLOCKS + 255) / 256, 256>>>();
    k_main<<<NBLOCKS, NTHREADS>>>(yhat, gpos, gori);
    k_final<<<1, 1>>>((float*)d_out);
}

// round 5
// speedup vs baseline: 1.4103x; 1.0008x over previous
#include <cuda_runtime.h>
#include <math.h>

#define NB 64
#define NS 4096
#define CHUNKS 16
#define CHUNK 256
#define NTHREADS 256
#define NWARPS 8
#define NBLOCKS (NB * CHUNKS)
#define NELEM (NB * NS)
#define EPSF 1e-6f
#define FULLMASK 0xffffffffu

// Pose = quaternion (w,x,y,z) + translation. 7 floats (vs 12 for 3x4 matrix).
struct Pose { float qw, qx, qy, qz, tx, ty, tz; };

__device__ float  g_agg[NBLOCKS][16];   // chunk aggregate   (E in [0..6], G in [8..14])
__device__ float  g_pre[NBLOCKS][16];   // chunk inclusive prefix
__device__ int    g_flag[NBLOCKS];      // generation-coded: 2*gen = agg ready, 2*gen+1 = prefix ready
__device__ double g_accum[6];           // sq_pos, ab_pos, odom_ang, sq_traj, ab_traj, traj_ang
__device__ int    g_gen = 1;            // generation (bumped by last block each launch)
__device__ int    g_done = 0;           // completed-block counter

__device__ __forceinline__ Pose pidentity() { return Pose{1.f, 0.f, 0.f, 0.f, 0.f, 0.f, 0.f}; }

// C = A then B (matches einsum x@y order): q = qa*qb, t = ta + rot(qa, tb)
__device__ __forceinline__ Pose pcompose(const Pose& A, const Pose& B) {
    Pose C;
    C.qw = A.qw*B.qw - A.qx*B.qx - A.qy*B.qy - A.qz*B.qz;
    C.qx = A.qw*B.qx + A.qx*B.qw + A.qy*B.qz - A.qz*B.qy;
    C.qy = A.qw*B.qy - A.qx*B.qz + A.qy*B.qw + A.qz*B.qx;
    C.qz = A.qw*B.qz + A.qx*B.qy - A.qy*B.qx + A.qz*B.qw;
    float t2x = 2.f * (A.qy*B.tz - A.qz*B.ty);
    float t2y = 2.f * (A.qz*B.tx - A.qx*B.tz);
    float t2z = 2.f * (A.qx*B.ty - A.qy*B.tx);
    C.tx = A.tx + B.tx + A.qw*t2x + (A.qy*t2z - A.qz*t2y);
    C.ty = A.ty + B.ty + A.qw*t2y + (A.qz*t2x - A.qx*t2z);
    C.tz = A.tz + B.tz + A.qw*t2z + (A.qx*t2y - A.qy*t2x);
    return C;
}

__device__ __forceinline__ Pose pshfl_up(const Pose& p, int off) {
    Pose r;
    r.qw = __shfl_up_sync(FULLMASK, p.qw, off);
    r.qx = __shfl_up_sync(FULLMASK, p.qx, off);
    r.qy = __shfl_up_sync(FULLMASK, p.qy, off);
    r.qz = __shfl_up_sync(FULLMASK, p.qz, off);
    r.tx = __shfl_up_sync(FULLMASK, p.tx, off);
    r.ty = __shfl_up_sync(FULLMASK, p.ty, off);
    r.tz = __shfl_up_sync(FULLMASK, p.tz, off);
    return r;
}

// Quaternion for R = Rz(c) @ Ry(b) @ Rx(a)  (matches reference euler_xyz_to_mat)
// Accurate sincosf: __sincosf caused rel_err 1.12e-3 (R3 fail) via acos amplification.
__device__ __forceinline__ void euler_to_quat(float a, float b, float c, Pose& P) {
    float sa, ca, sb, cb, sc, cc;
    sincosf(0.5f * a, &sa, &ca);
    sincosf(0.5f * b, &sb, &cb);
    sincosf(0.5f * c, &sc, &cc);
    P.qw = cc*cb*ca + sc*sb*sa;
    P.qx = cc*cb*sa - sc*sb*ca;
    P.qy = cc*sb*ca + sc*cb*sa;
    P.qz = sc*cb*ca - cc*sb*sa;
}

// arccos((trace(R1 R2^T)-1)/2). For (possibly non-unit) quats:
// cos = 2*dot(q1,q2)^2/(|q1|^2 |q2|^2) - 1  -- norm drift cancels exactly.
__device__ __forceinline__ float rot_angle(const Pose& A, const Pose& B) {
    float d  = A.qw*B.qw + A.qx*B.qx + A.qy*B.qy + A.qz*B.qz;
    float n1 = A.qw*A.qw + A.qx*A.qx + A.qy*A.qy + A.qz*A.qz;
    float n2 = B.qw*B.qw + B.qx*B.qx + B.qy*B.qy + B.qz*B.qz;
    float c = 2.f * d * d / (n1 * n2) - 1.f;
    c = fminf(fmaxf(c, -1.f + EPSF), 1.f - EPSF);
    return acosf(c);
}

__device__ __forceinline__ void pstore_s(float* p, const Pose& x) {
    p[0]=x.qw; p[1]=x.qx; p[2]=x.qy; p[3]=x.qz; p[4]=x.tx; p[5]=x.ty; p[6]=x.tz;
}
__device__ __forceinline__ Pose pload_s(const float* p) {
    Pose x;
    x.qw=p[0]; x.qx=p[1]; x.qy=p[2]; x.qz=p[3]; x.tx=p[4]; x.ty=p[5]; x.tz=p[6];
    return x;
}
__device__ __forceinline__ void pair_store_g(float* p, const Pose& e, const Pose& g) {
    *(float4*)(p)      = make_float4(e.qw, e.qx, e.qy, e.qz);
    *(float4*)(p + 4)  = make_float4(e.tx, e.ty, e.tz, 0.f);
    *(float4*)(p + 8)  = make_float4(g.qw, g.qx, g.qy, g.qz);
    *(float4*)(p + 12) = make_float4(g.tx, g.ty, g.tz, 0.f);
}
__device__ __forceinline__ void pair_load_g(const float* p, Pose& e, Pose& g) {
    float4 a = *(const float4*)(p),     b = *(const float4*)(p + 4);
    float4 c = *(const float4*)(p + 8), d = *(const float4*)(p + 12);
    e.qw=a.x; e.qx=a.y; e.qy=a.z; e.qz=a.w; e.tx=b.x; e.ty=b.y; e.tz=b.z;
    g.qw=c.x; g.qx=c.y; g.qy=c.z; g.qz=c.w; g.tx=d.x; g.ty=d.y; g.tz=d.z;
}

__device__ __forceinline__ void block_reduce6_atomic(float v[6]) {
#pragma unroll
    for (int o = 16; o > 0; o >>= 1)
#pragma unroll
        for (int j = 0; j < 6; j++) v[j] += __shfl_down_sync(FULLMASK, v[j], o);
    __shared__ float w[6][NWARPS];
    int lane = threadIdx.x & 31, wid = threadIdx.x >> 5;
    if (lane == 0)
#pragma unroll
        for (int j = 0; j < 6; j++) w[j][wid] = v[j];
    __syncthreads();
    if (threadIdx.x < 6) {
        double s = 0.0;
#pragma unroll
        for (int i = 0; i < NWARPS; i++) s += (double)w[threadIdx.x][i];
        atomicAdd(&g_accum[threadIdx.x], s);
    }
}

// Single fused kernel: pose build + block scan + decoupled lookback (generation-
// coded flags, no init pass) + all losses + last-block finalize (no final pass).
__global__ void __launch_bounds__(NTHREADS) k_main(
    const float* __restrict__ yhat, const float* __restrict__ gpos,
    const float* __restrict__ gori, float* __restrict__ out) {
    __shared__ float sw[2][NWARPS][8];
    __shared__ float sexc[2][8];
    int tid = threadIdx.x, lane = tid & 31, wid = tid >> 5;
    int bid = blockIdx.x;
    int batch = bid >> 4, chunk = bid & (CHUNKS - 1);
    int s = chunk * CHUNK + tid;
    int idx = batch * NS + s;

    // ---- build poses + odometry pointwise terms ----
    const float* y  = yhat + (size_t)idx * 6;
    const float* gp = gpos + (size_t)idx * 3;
    const float* go = gori + (size_t)idx * 3;
    Pose E, G;
    euler_to_quat(y[0], y[1], y[2], E);
    E.tx = y[3]; E.ty = y[4]; E.tz = y[5];
    euler_to_quat(go[0], go[1], go[2], G);
    G.tx = gp[0]; G.ty = gp[1]; G.tz = gp[2];

    float acc[6];
    acc[0] = 0.f; acc[1] = 0.f;
#pragma unroll
    for (int k = 0; k < 3; k++) {
        float d = (&E.tx)[k] - (&G.tx)[k];
        acc[0] = fmaf(d, d, acc[0]);
        acc[1] += fabsf(d);
    }
    acc[2] = rot_angle(E, G);
    if (s == 0) { E = pidentity(); G = pidentity(); }  // shifted[...,0] = I

    // ---- warp-level inclusive scan (left compose) ----
#pragma unroll
    for (int off = 1; off < 32; off <<= 1) {
        Pose le = pshfl_up(E, off), lg = pshfl_up(G, off);
        if (lane >= off) { E = pcompose(le, E); G = pcompose(lg, G); }
    }
    if (lane == 31) { pstore_s(sw[0][wid], E); pstore_s(sw[1][wid], G); }
    __syncthreads();

    // ---- cross-warp scan (warp 0) ----
    if (wid == 0) {
        Pose te = (lane < NWARPS) ? pload_s(sw[0][lane]) : pidentity();
        Pose tg = (lane < NWARPS) ? pload_s(sw[1][lane]) : pidentity();
#pragma unroll
        for (int off = 1; off < NWARPS; off <<= 1) {
            Pose le = pshfl_up(te, off), lg = pshfl_up(tg, off);
            if (lane >= off && lane < NWARPS) { te = pcompose(le, te); tg = pcompose(lg, tg); }
        }
        if (lane < NWARPS) { pstore_s(sw[0][lane], te); pstore_s(sw[1][lane], tg); }
    }
    __syncthreads();

    // ---- thread 0: publish aggregate, lookback, publish prefix ----
    if (tid == 0) {
        int gen = *(volatile int*)&g_gen;
        int fagg = 2 * gen, fpre = 2 * gen + 1;
        Pose aE = pload_s(sw[0][NWARPS - 1]);
        Pose aG = pload_s(sw[1][NWARPS - 1]);
        if (chunk < CHUNKS - 1) {
            pair_store_g(g_agg[bid], aE, aG);
            __threadfence();
            atomicExch(&g_flag[bid], fagg);
        }
        Pose excE = pidentity(), excG = pidentity();
        if (chunk > 0) {
            Pose accE = pidentity(), accG = pidentity();
            bool have = false;
            int base = batch * CHUNKS;
            for (int i = bid - 1; i >= base; --i) {
                int f;
                volatile int* vf = g_flag;
                while ((f = vf[i]) < fagg) { __nanosleep(32); }
                __threadfence();
                Pose pE, pG;
                if (f == fpre) {
                    pair_load_g(g_pre[i], pE, pG);
                    excE = pcompose(pE, accE);
                    excG = pcompose(pG, accG);
                    have = true;
                    break;
                } else {
                    pair_load_g(g_agg[i], pE, pG);
                    accE = pcompose(pE, accE);
                    accG = pcompose(pG, accG);
                }
            }
            if (!have) { excE = accE; excG = accG; }
        }
        if (chunk < CHUNKS - 1) {
            Pose pE = pcompose(excE, aE), pG = pcompose(excG, aG);
            pair_store_g(g_pre[bid], pE, pG);
            __threadfence();
            atomicExch(&g_flag[bid], fpre);
        }
        pstore_s(sexc[0], excE);
        pstore_s(sexc[1], excG);
    }
    __syncthreads();

    // ---- apply prefixes, trajectory losses ----
    Pose preE = pload_s(sexc[0]);
    Pose preG = pload_s(sexc[1]);
    if (wid > 0) {
        preE = pcompose(preE, pload_s(sw[0][wid - 1]));
        preG = pcompose(preG, pload_s(sw[1][wid - 1]));
    }
    Pose CE = pcompose(preE, E);
    Pose CG = pcompose(preG, G);

    acc[3] = 0.f; acc[4] = 0.f;
#pragma unroll
    for (int k = 0; k < 3; k++) {
        float d = (&CE.tx)[k] - (&CG.tx)[k];
        acc[3] = fmaf(d, d, acc[3]);
        acc[4] += fabsf(d);
    }
    acc[5] = rot_angle(CE, CG);
    block_reduce6_atomic(acc);
    __syncthreads();

    // ---- last block finalizes (threadfence-reduction pattern) ----
    if (tid == 0) {
        __threadfence();
        int old = atomicAdd(&g_done, 1);
        if (old == NBLOCKS - 1) {
            __threadfence();
            const double n3 = (double)NELEM * 3.0, n1 = (double)NELEM;
            double odom = g_accum[2] / n1 + (g_accum[0] / n3 + g_accum[1] / n3);
            double traj = g_accum[5] / n1 + (g_accum[3] / n3 + g_accum[4] / n3);
            out[0] = (float)(0.5 * odom + 0.5 * traj);
            // reset state for next graph replay
#pragma unroll
            for (int j = 0; j < 6; j++) g_accum[j] = 0.0;
            g_done = 0;
            __threadfence();
            g_gen = *(volatile int*)&g_gen + 1;
        }
    }
}

extern "C" void kernel_launch(void* const* d_in, const int* in_sizes, int n_in,
                              void* d_out, int out_size) {
    const float* yhat = (const float*)d_in[0];
    const float* gpos = (const float*)d_in[1];
    const float* gori = (const float*)d_in[2];
    k_main<<<NBLOCKS, NTHREADS>>>(yhat, gpos, gori, (float*)d_out);
}

// round 6
// speedup vs baseline: 2.0731x; 1.4700x over previous
#include <cuda_runtime.h>
#include <math.h>

#define NB 64
#define NS 4096
#define CHUNKS 8
#define CHUNK 512
#define NTHREADS 256
#define NWARPS 8
#define EPT 2
#define NBLOCKS (NB * CHUNKS)
#define NELEM (NB * NS)
#define EPSF 1e-6f
#define FULLMASK 0xffffffffu

// Pose = quaternion (w,x,y,z) + translation.
struct Pose { float qw, qx, qy, qz, tx, ty, tz; };

__device__ float  g_agg[NBLOCKS][16];   // chunk aggregate   (E in [0..6], G in [8..14])
__device__ float  g_pre[NBLOCKS][16];   // chunk inclusive prefix
__device__ int    g_flag[NBLOCKS];      // generation-coded: 2*gen = agg ready, 2*gen+1 = prefix ready
__device__ double g_accum[6];           // sq_pos, ab_pos, odom_ang, sq_traj, ab_traj, traj_ang
__device__ int    g_gen = 1;
__device__ int    g_done = 0;

__device__ __forceinline__ Pose pidentity() { return Pose{1.f, 0.f, 0.f, 0.f, 0.f, 0.f, 0.f}; }

// C = A then B (matches einsum x@y order): q = qa*qb, t = ta + rot(qa, tb)
__device__ __forceinline__ Pose pcompose(const Pose& A, const Pose& B) {
    Pose C;
    C.qw = A.qw*B.qw - A.qx*B.qx - A.qy*B.qy - A.qz*B.qz;
    C.qx = A.qw*B.qx + A.qx*B.qw + A.qy*B.qz - A.qz*B.qy;
    C.qy = A.qw*B.qy - A.qx*B.qz + A.qy*B.qw + A.qz*B.qx;
    C.qz = A.qw*B.qz + A.qx*B.qy - A.qy*B.qx + A.qz*B.qw;
    float t2x = 2.f * (A.qy*B.tz - A.qz*B.ty);
    float t2y = 2.f * (A.qz*B.tx - A.qx*B.tz);
    float t2z = 2.f * (A.qx*B.ty - A.qy*B.tx);
    C.tx = A.tx + B.tx + A.qw*t2x + (A.qy*t2z - A.qz*t2y);
    C.ty = A.ty + B.ty + A.qw*t2y + (A.qz*t2x - A.qx*t2z);
    C.tz = A.tz + B.tz + A.qw*t2z + (A.qx*t2y - A.qy*t2x);
    return C;
}

__device__ __forceinline__ void pnormq(Pose& p) {
    float s = rsqrtf(p.qw*p.qw + p.qx*p.qx + p.qy*p.qy + p.qz*p.qz);
    p.qw *= s; p.qx *= s; p.qy *= s; p.qz *= s;
}

__device__ __forceinline__ Pose pshfl_up(const Pose& p, int off) {
    Pose r;
    r.qw = __shfl_up_sync(FULLMASK, p.qw, off);
    r.qx = __shfl_up_sync(FULLMASK, p.qx, off);
    r.qy = __shfl_up_sync(FULLMASK, p.qy, off);
    r.qz = __shfl_up_sync(FULLMASK, p.qz, off);
    r.tx = __shfl_up_sync(FULLMASK, p.tx, off);
    r.ty = __shfl_up_sync(FULLMASK, p.ty, off);
    r.tz = __shfl_up_sync(FULLMASK, p.tz, off);
    return r;
}

// Quaternion for R = Rz(c) @ Ry(b) @ Rx(a). Fast trig: safe because the angle
// formula below is norm-invariant and published prefixes are renormalized.
__device__ __forceinline__ void euler_to_quat(float a, float b, float c, Pose& P) {
    float sa, ca, sb, cb, sc, cc;
    __sincosf(0.5f * a, &sa, &ca);
    __sincosf(0.5f * b, &sb, &cb);
    __sincosf(0.5f * c, &sc, &cc);
    P.qw = cc*cb*ca + sc*sb*sa;
    P.qx = cc*cb*sa - sc*sb*ca;
    P.qy = cc*sb*ca + sc*cb*sa;
    P.qz = sc*cb*ca - cc*sb*sa;
}

// arccos((trace(R1 R2^T)-1)/2); for non-unit quats: cos = 2*dot^2/(n1*n2) - 1.
__device__ __forceinline__ float rot_angle(const Pose& A, const Pose& B) {
    float d  = A.qw*B.qw + A.qx*B.qx + A.qy*B.qy + A.qz*B.qz;
    float n1 = A.qw*A.qw + A.qx*A.qx + A.qy*A.qy + A.qz*A.qz;
    float n2 = B.qw*B.qw + B.qx*B.qx + B.qy*B.qy + B.qz*B.qz;
    float c = 2.f * d * d / (n1 * n2) - 1.f;
    c = fminf(fmaxf(c, -1.f + EPSF), 1.f - EPSF);
    return acosf(c);
}

__device__ __forceinline__ void pstore_s(float* p, const Pose& x) {
    p[0]=x.qw; p[1]=x.qx; p[2]=x.qy; p[3]=x.qz; p[4]=x.tx; p[5]=x.ty; p[6]=x.tz;
}
__device__ __forceinline__ Pose pload_s(const float* p) {
    Pose x;
    x.qw=p[0]; x.qx=p[1]; x.qy=p[2]; x.qz=p[3]; x.tx=p[4]; x.ty=p[5]; x.tz=p[6];
    return x;
}
__device__ __forceinline__ void pair_store_g(float* p, const Pose& e, const Pose& g) {
    *(float4*)(p)      = make_float4(e.qw, e.qx, e.qy, e.qz);
    *(float4*)(p + 4)  = make_float4(e.tx, e.ty, e.tz, 0.f);
    *(float4*)(p + 8)  = make_float4(g.qw, g.qx, g.qy, g.qz);
    *(float4*)(p + 12) = make_float4(g.tx, g.ty, g.tz, 0.f);
}
__device__ __forceinline__ void pair_load_g(const float* p, Pose& e, Pose& g) {
    float4 a = *(const float4*)(p),     b = *(const float4*)(p + 4);
    float4 c = *(const float4*)(p + 8), d = *(const float4*)(p + 12);
    e.qw=a.x; e.qx=a.y; e.qy=a.z; e.qz=a.w; e.tx=b.x; e.ty=b.y; e.tz=b.z;
    g.qw=c.x; g.qx=c.y; g.qy=c.z; g.qz=c.w; g.tx=d.x; g.ty=d.y; g.tz=d.z;
}

__device__ __forceinline__ void block_reduce6_atomic(float v[6]) {
#pragma unroll
    for (int o = 16; o > 0; o >>= 1)
#pragma unroll
        for (int j = 0; j < 6; j++) v[j] += __shfl_down_sync(FULLMASK, v[j], o);
    __shared__ float w[6][NWARPS];
    int lane = threadIdx.x & 31, wid = threadIdx.x >> 5;
    if (lane == 0)
#pragma unroll
        for (int j = 0; j < 6; j++) w[j][wid] = v[j];
    __syncthreads();
    if (threadIdx.x < 6) {
        double s = 0.0;
#pragma unroll
        for (int i = 0; i < NWARPS; i++) s += (double)w[threadIdx.x][i];
        atomicAdd(&g_accum[threadIdx.x], s);
    }
}

// Single fused kernel, EPT=2: pose build + thread-serial pair + warp scan +
// decoupled lookback + losses + last-block finalize.
__global__ void __launch_bounds__(NTHREADS) k_main(
    const float* __restrict__ yhat, const float* __restrict__ gpos,
    const float* __restrict__ gori, float* __restrict__ out) {
    __shared__ float sP[NTHREADS][15];     // elem-0 poses: E in [0..6], G in [7..13]
    __shared__ float sw[2][NWARPS][8];
    __shared__ float sexc[2][8];
    int tid = threadIdx.x, lane = tid & 31, wid = tid >> 5;
    int bid = blockIdx.x;
    int batch = bid >> 3, chunk = bid & (CHUNKS - 1);
    int s0 = chunk * CHUNK + tid * EPT;
    int idx0 = batch * NS + s0;

    // ---- inputs (vectorized; idx0 even -> 16B/8B aligned) ----
    const float* y = yhat + (size_t)idx0 * 6;
    float4 y0 = *(const float4*)(y), y1 = *(const float4*)(y + 4), y2 = *(const float4*)(y + 8);
    const float* gp = gpos + (size_t)idx0 * 3;
    float2 p0 = *(const float2*)(gp), p1 = *(const float2*)(gp + 2), p2 = *(const float2*)(gp + 4);
    const float* go = gori + (size_t)idx0 * 3;
    float2 o0 = *(const float2*)(go), o1 = *(const float2*)(go + 2), o2 = *(const float2*)(go + 4);

    // ---- build poses, odometry pointwise terms ----
    Pose E0, G0, E1, G1;
    euler_to_quat(y0.x, y0.y, y0.z, E0);
    E0.tx = y0.w; E0.ty = y1.x; E0.tz = y1.y;
    euler_to_quat(y1.z, y1.w, y2.x, E1);
    E1.tx = y2.y; E1.ty = y2.z; E1.tz = y2.w;
    euler_to_quat(o0.x, o0.y, o1.x, G0);
    G0.tx = p0.x; G0.ty = p0.y; G0.tz = p1.x;
    euler_to_quat(o1.y, o2.x, o2.y, G1);
    G1.tx = p1.y; G1.ty = p2.x; G1.tz = p2.y;

    float acc[6];
    acc[0] = 0.f; acc[1] = 0.f;
#pragma unroll
    for (int k = 0; k < 3; k++) {
        float d0 = (&E0.tx)[k] - (&G0.tx)[k];
        float d1 = (&E1.tx)[k] - (&G1.tx)[k];
        acc[0] = fmaf(d0, d0, fmaf(d1, d1, acc[0]));
        acc[1] += fabsf(d0) + fabsf(d1);
    }
    acc[2] = rot_angle(E0, G0) + rot_angle(E1, G1);
    if (s0 == 0) { E0 = pidentity(); G0 = pidentity(); }  // shifted[...,0] = I

    // Stash elem-0 poses (needed again after the scan); elem-1 never is:
    // its cumulative equals base ∘ thread_inclusive.
    pstore_s(&sP[tid][0], E0);
    pstore_s(&sP[tid][7], G0);

    // ---- thread aggregate + warp-level inclusive scan ----
    Pose IE = pcompose(E0, E1);
    Pose IG = pcompose(G0, G1);
#pragma unroll
    for (int off = 1; off < 32; off <<= 1) {
        Pose le = pshfl_up(IE, off), lg = pshfl_up(IG, off);
        if (lane >= off) { IE = pcompose(le, IE); IG = pcompose(lg, IG); }
    }
    if (lane == 31) { pstore_s(sw[0][wid], IE); pstore_s(sw[1][wid], IG); }
    __syncthreads();

    // ---- cross-warp scan (warp 0) ----
    if (wid == 0) {
        Pose te = (lane < NWARPS) ? pload_s(sw[0][lane]) : pidentity();
        Pose tg = (lane < NWARPS) ? pload_s(sw[1][lane]) : pidentity();
#pragma unroll
        for (int off = 1; off < NWARPS; off <<= 1) {
            Pose le = pshfl_up(te, off), lg = pshfl_up(tg, off);
            if (lane >= off && lane < NWARPS) { te = pcompose(le, te); tg = pcompose(lg, tg); }
        }
        if (lane < NWARPS) { pstore_s(sw[0][lane], te); pstore_s(sw[1][lane], tg); }
    }
    __syncthreads();

    // ---- thread 0: publish aggregate, lookback (depth <= 7), publish prefix ----
    if (tid == 0) {
        int gen = *(volatile int*)&g_gen;
        int fagg = 2 * gen, fpre = 2 * gen + 1;
        Pose aE = pload_s(sw[0][NWARPS - 1]);
        Pose aG = pload_s(sw[1][NWARPS - 1]);
        pnormq(aE); pnormq(aG);   // cap norm drift at chunk length
        if (chunk < CHUNKS - 1) {
            pair_store_g(g_agg[bid], aE, aG);
            __threadfence();
            atomicExch(&g_flag[bid], fagg);
        }
        Pose excE = pidentity(), excG = pidentity();
        if (chunk > 0) {
            Pose accE = pidentity(), accG = pidentity();
            bool have = false;
            int base = batch * CHUNKS;
            for (int i = bid - 1; i >= base; --i) {
                int f;
                volatile int* vf = g_flag;
                while ((f = vf[i]) < fagg) { __nanosleep(20); }
                __threadfence();
                Pose pE, pG;
                if (f == fpre) {
                    pair_load_g(g_pre[i], pE, pG);
                    excE = pcompose(pE, accE);
                    excG = pcompose(pG, accG);
                    have = true;
                    break;
                } else {
                    pair_load_g(g_agg[i], pE, pG);
                    accE = pcompose(pE, accE);
                    accG = pcompose(pG, accG);
                }
            }
            if (!have) { excE = accE; excG = accG; }
            pnormq(excE); pnormq(excG);
        }
        if (chunk < CHUNKS - 1) {
            Pose pE = pcompose(excE, aE), pG = pcompose(excG, aG);
            pnormq(pE); pnormq(pG);
            pair_store_g(g_pre[bid], pE, pG);
            __threadfence();
            atomicExch(&g_flag[bid], fpre);
        }
        pstore_s(sexc[0], excE);
        pstore_s(sexc[1], excG);
    }
    __syncthreads();

    // ---- apply prefixes, trajectory losses (2 elems) ----
    Pose baseE = pload_s(sexc[0]);
    Pose baseG = pload_s(sexc[1]);
    if (wid > 0) {
        baseE = pcompose(baseE, pload_s(sw[0][wid - 1]));
        baseG = pcompose(baseG, pload_s(sw[1][wid - 1]));
    }
    // lane-exclusive via shfl of the (still live) inclusive registers
    Pose LEe = pshfl_up(IE, 1), LEg = pshfl_up(IG, 1);
    Pose preE = (lane == 0) ? baseE : pcompose(baseE, LEe);
    Pose preG = (lane == 0) ? baseG : pcompose(baseG, LEg);

    Pose C0E = pcompose(preE, pload_s(&sP[tid][0]));
    Pose C0G = pcompose(preG, pload_s(&sP[tid][7]));
    Pose C1E = pcompose(baseE, IE);
    Pose C1G = pcompose(baseG, IG);

    acc[3] = 0.f; acc[4] = 0.f;
#pragma unroll
    for (int k = 0; k < 3; k++) {
        float d0 = (&C0E.tx)[k] - (&C0G.tx)[k];
        float d1 = (&C1E.tx)[k] - (&C1G.tx)[k];
        acc[3] = fmaf(d0, d0, fmaf(d1, d1, acc[3]));
        acc[4] += fabsf(d0) + fabsf(d1);
    }
    acc[5] = rot_angle(C0E, C0G) + rot_angle(C1E, C1G);
    block_reduce6_atomic(acc);
    __syncthreads();

    // ---- last block finalizes ----
    if (tid == 0) {
        __threadfence();
        int old = atomicAdd(&g_done, 1);
        if (old == NBLOCKS - 1) {
            __threadfence();
            const double n3 = (double)NELEM * 3.0, n1 = (double)NELEM;
            double odom = g_accum[2] / n1 + (g_accum[0] / n3 + g_accum[1] / n3);
            double traj = g_accum[5] / n1 + (g_accum[3] / n3 + g_accum[4] / n3);
            out[0] = (float)(0.5 * odom + 0.5 * traj);
#pragma unroll
            for (int j = 0; j < 6; j++) g_accum[j] = 0.0;
            g_done = 0;
            __threadfence();
            g_gen = *(volatile int*)&g_gen + 1;
        }
    }
}

extern "C" void kernel_launch(void* const* d_in, const int* in_sizes, int n_in,
                              void* d_out, int out_size) {
    const float* yhat = (const float*)d_in[0];
    const float* gpos = (const float*)d_in[1];
    const float* gori = (const float*)d_in[2];
    k_main<<<NBLOCKS, NTHREADS>>>(yhat, gpos, gori, (float*)d_out);
}

// round 7
// speedup vs baseline: 2.6357x; 1.2713x over previous
#include <cuda_runtime.h>
#include <math.h>

#define NB 64
#define NS 4096
#define CHUNKS 8
#define CHUNK 512
#define NTHREADS 128
#define NWARPS 4
#define EPT 4
#define NBLOCKS (NB * CHUNKS)
#define NELEM (NB * NS)
#define EPSF 1e-6f
#define FULLMASK 0xffffffffu
#define SP_STRIDE 43   // 42 floats used; 43 => gcd(43,32)=1, conflict-free

// Pose = quaternion (w,x,y,z) + translation.
struct Pose { float qw, qx, qy, qz, tx, ty, tz; };

__device__ float  g_agg[NBLOCKS][16];   // chunk aggregate   (E in [0..6], G in [8..14])
__device__ float  g_pre[NBLOCKS][16];   // chunk inclusive prefix
__device__ int    g_flag[NBLOCKS];      // generation-coded: 2*gen = agg ready, 2*gen+1 = prefix ready
__device__ double g_accum[6];           // sq_pos, ab_pos, odom_ang, sq_traj, ab_traj, traj_ang
__device__ int    g_gen = 1;
__device__ int    g_done = 0;

__device__ __forceinline__ Pose pidentity() { return Pose{1.f, 0.f, 0.f, 0.f, 0.f, 0.f, 0.f}; }

// C = A then B (matches einsum x@y order): q = qa*qb, t = ta + rot(qa, tb)
__device__ __forceinline__ Pose pcompose(const Pose& A, const Pose& B) {
    Pose C;
    C.qw = A.qw*B.qw - A.qx*B.qx - A.qy*B.qy - A.qz*B.qz;
    C.qx = A.qw*B.qx + A.qx*B.qw + A.qy*B.qz - A.qz*B.qy;
    C.qy = A.qw*B.qy - A.qx*B.qz + A.qy*B.qw + A.qz*B.qx;
    C.qz = A.qw*B.qz + A.qx*B.qy - A.qy*B.qx + A.qz*B.qw;
    float t2x = 2.f * (A.qy*B.tz - A.qz*B.ty);
    float t2y = 2.f * (A.qz*B.tx - A.qx*B.tz);
    float t2z = 2.f * (A.qx*B.ty - A.qy*B.tx);
    C.tx = A.tx + B.tx + A.qw*t2x + (A.qy*t2z - A.qz*t2y);
    C.ty = A.ty + B.ty + A.qw*t2y + (A.qz*t2x - A.qx*t2z);
    C.tz = A.tz + B.tz + A.qw*t2z + (A.qx*t2y - A.qy*t2x);
    return C;
}

__device__ __forceinline__ void pnormq(Pose& p) {
    float s = rsqrtf(p.qw*p.qw + p.qx*p.qx + p.qy*p.qy + p.qz*p.qz);
    p.qw *= s; p.qx *= s; p.qy *= s; p.qz *= s;
}

__device__ __forceinline__ Pose pshfl_up(const Pose& p, int off) {
    Pose r;
    r.qw = __shfl_up_sync(FULLMASK, p.qw, off);
    r.qx = __shfl_up_sync(FULLMASK, p.qx, off);
    r.qy = __shfl_up_sync(FULLMASK, p.qy, off);
    r.qz = __shfl_up_sync(FULLMASK, p.qz, off);
    r.tx = __shfl_up_sync(FULLMASK, p.tx, off);
    r.ty = __shfl_up_sync(FULLMASK, p.ty, off);
    r.tz = __shfl_up_sync(FULLMASK, p.tz, off);
    return r;
}

// Quaternion for R = Rz(c) @ Ry(b) @ Rx(a). Fast trig is safe: the angle
// formula is norm-invariant and published prefixes are renormalized.
__device__ __forceinline__ void euler_to_quat(float a, float b, float c, Pose& P) {
    float sa, ca, sb, cb, sc, cc;
    __sincosf(0.5f * a, &sa, &ca);
    __sincosf(0.5f * b, &sb, &cb);
    __sincosf(0.5f * c, &sc, &cc);
    P.qw = cc*cb*ca + sc*sb*sa;
    P.qx = cc*cb*sa - sc*sb*ca;
    P.qy = cc*sb*ca + sc*cb*sa;
    P.qz = sc*cb*ca - cc*sb*sa;
}

// arccos((trace(R1 R2^T)-1)/2); for non-unit quats: cos = 2*dot^2/(n1*n2) - 1.
__device__ __forceinline__ float rot_angle(const Pose& A, const Pose& B) {
    float d  = A.qw*B.qw + A.qx*B.qx + A.qy*B.qy + A.qz*B.qz;
    float n1 = A.qw*A.qw + A.qx*A.qx + A.qy*A.qy + A.qz*A.qz;
    float n2 = B.qw*B.qw + B.qx*B.qx + B.qy*B.qy + B.qz*B.qz;
    float c = 2.f * d * d / (n1 * n2) - 1.f;
    c = fminf(fmaxf(c, -1.f + EPSF), 1.f - EPSF);
    return acosf(c);
}

__device__ __forceinline__ void pstore_s(float* p, const Pose& x) {
    p[0]=x.qw; p[1]=x.qx; p[2]=x.qy; p[3]=x.qz; p[4]=x.tx; p[5]=x.ty; p[6]=x.tz;
}
__device__ __forceinline__ Pose pload_s(const float* p) {
    Pose x;
    x.qw=p[0]; x.qx=p[1]; x.qy=p[2]; x.qz=p[3]; x.tx=p[4]; x.ty=p[5]; x.tz=p[6];
    return x;
}
__device__ __forceinline__ void pair_store_g(float* p, const Pose& e, const Pose& g) {
    *(float4*)(p)      = make_float4(e.qw, e.qx, e.qy, e.qz);
    *(float4*)(p + 4)  = make_float4(e.tx, e.ty, e.tz, 0.f);
    *(float4*)(p + 8)  = make_float4(g.qw, g.qx, g.qy, g.qz);
    *(float4*)(p + 12) = make_float4(g.tx, g.ty, g.tz, 0.f);
}
__device__ __forceinline__ void pair_load_g(const float* p, Pose& e, Pose& g) {
    float4 a = *(const float4*)(p),     b = *(const float4*)(p + 4);
    float4 c = *(const float4*)(p + 8), d = *(const float4*)(p + 12);
    e.qw=a.x; e.qx=a.y; e.qy=a.z; e.qz=a.w; e.tx=b.x; e.ty=b.y; e.tz=b.z;
    g.qw=c.x; g.qx=c.y; g.qy=c.z; g.qz=c.w; g.tx=d.x; g.ty=d.y; g.tz=d.z;
}

__device__ __forceinline__ void block_reduce6_atomic(float v[6]) {
#pragma unroll
    for (int o = 16; o > 0; o >>= 1)
#pragma unroll
        for (int j = 0; j < 6; j++) v[j] += __shfl_down_sync(FULLMASK, v[j], o);
    __shared__ float w[6][NWARPS];
    int lane = threadIdx.x & 31, wid = threadIdx.x >> 5;
    if (lane == 0)
#pragma unroll
        for (int j = 0; j < 6; j++) w[j][wid] = v[j];
    __syncthreads();
    if (threadIdx.x < 6) {
        double s = 0.0;
#pragma unroll
        for (int i = 0; i < NWARPS; i++) s += (double)w[threadIdx.x][i];
        atomicAdd(&g_accum[threadIdx.x], s);
    }
}

// Single fused kernel, EPT=4: pose build + thread-serial prefixes + warp scan +
// decoupled lookback + losses + last-block finalize.
__global__ void __launch_bounds__(NTHREADS) k_main(
    const float* __restrict__ yhat, const float* __restrict__ gpos,
    const float* __restrict__ gori, float* __restrict__ out) {
    __shared__ float sP[NTHREADS][SP_STRIDE];  // E prefixes 0/7/14, G prefixes 21/28/35
    __shared__ float sw[2][NWARPS][8];
    __shared__ float sexc[2][8];
    int tid = threadIdx.x, lane = tid & 31, wid = tid >> 5;
    int bid = blockIdx.x;
    int batch = bid >> 3, chunk = bid & (CHUNKS - 1);
    int s0 = chunk * CHUNK + tid * EPT;
    int idx0 = batch * NS + s0;

    // ---- inputs (all float4: idx0 % 4 == 0 => 6*idx0, 3*idx0 are /4) ----
    const float4* y4 = (const float4*)(yhat + (size_t)idx0 * 6);
    float4 y0 = y4[0], y1 = y4[1], y2 = y4[2], y3 = y4[3], y4v = y4[4], y5 = y4[5];
    const float4* gp4 = (const float4*)(gpos + (size_t)idx0 * 3);
    float4 p0 = gp4[0], p1 = gp4[1], p2 = gp4[2];
    const float4* go4 = (const float4*)(gori + (size_t)idx0 * 3);
    float4 q0 = go4[0], q1 = go4[1], q2 = go4[2];

    float ea[4][3] = {{y0.x,y0.y,y0.z},{y1.z,y1.w,y2.x},{y3.x,y3.y,y3.z},{y4v.z,y4v.w,y5.x}};
    float et[4][3] = {{y0.w,y1.x,y1.y},{y2.y,y2.z,y2.w},{y3.w,y4v.x,y4v.y},{y5.y,y5.z,y5.w}};
    float ga[4][3] = {{q0.x,q0.y,q0.z},{q0.w,q1.x,q1.y},{q1.z,q1.w,q2.x},{q2.y,q2.z,q2.w}};
    float gt[4][3] = {{p0.x,p0.y,p0.z},{p0.w,p1.x,p1.y},{p1.z,p1.w,p2.x},{p2.y,p2.z,p2.w}};

    // ---- build poses, odom terms, thread-serial prefixes ----
    float acc[6];
    acc[0] = 0.f; acc[1] = 0.f; acc[2] = 0.f;
    Pose IE, IG;
#pragma unroll
    for (int i = 0; i < EPT; i++) {
        Pose E, G;
        euler_to_quat(ea[i][0], ea[i][1], ea[i][2], E);
        E.tx = et[i][0]; E.ty = et[i][1]; E.tz = et[i][2];
        euler_to_quat(ga[i][0], ga[i][1], ga[i][2], G);
        G.tx = gt[i][0]; G.ty = gt[i][1]; G.tz = gt[i][2];
#pragma unroll
        for (int k = 0; k < 3; k++) {
            float d = (&E.tx)[k] - (&G.tx)[k];
            acc[0] = fmaf(d, d, acc[0]);
            acc[1] += fabsf(d);
        }
        acc[2] += rot_angle(E, G);
        if (s0 == 0 && i == 0) { E = pidentity(); G = pidentity(); }  // shifted[0] = I
        if (i == 0) { IE = E; IG = G; }
        else        { IE = pcompose(IE, E); IG = pcompose(IG, G); }
        if (i < EPT - 1) {
            pstore_s(&sP[tid][i * 7], IE);
            pstore_s(&sP[tid][21 + i * 7], IG);
        }
    }

    // ---- warp-level inclusive scan over thread aggregates ----
#pragma unroll
    for (int off = 1; off < 32; off <<= 1) {
        Pose le = pshfl_up(IE, off), lg = pshfl_up(IG, off);
        if (lane >= off) { IE = pcompose(le, IE); IG = pcompose(lg, IG); }
    }
    if (lane == 31) { pstore_s(sw[0][wid], IE); pstore_s(sw[1][wid], IG); }
    __syncthreads();

    // ---- cross-warp scan (warp 0, 4 entries -> 2 steps) ----
    if (wid == 0) {
        Pose te = (lane < NWARPS) ? pload_s(sw[0][lane]) : pidentity();
        Pose tg = (lane < NWARPS) ? pload_s(sw[1][lane]) : pidentity();
#pragma unroll
        for (int off = 1; off < NWARPS; off <<= 1) {
            Pose le = pshfl_up(te, off), lg = pshfl_up(tg, off);
            if (lane >= off && lane < NWARPS) { te = pcompose(le, te); tg = pcompose(lg, tg); }
        }
        if (lane < NWARPS) { pstore_s(sw[0][lane], te); pstore_s(sw[1][lane], tg); }
    }
    __syncthreads();

    // ---- thread 0: publish aggregate, lookback (depth <= 7), publish prefix ----
    if (tid == 0) {
        int gen = *(volatile int*)&g_gen;
        int fagg = 2 * gen, fpre = 2 * gen + 1;
        Pose aE = pload_s(sw[0][NWARPS - 1]);
        Pose aG = pload_s(sw[1][NWARPS - 1]);
        pnormq(aE); pnormq(aG);   // cap norm drift at chunk length
        if (chunk < CHUNKS - 1) {
            pair_store_g(g_agg[bid], aE, aG);
            __threadfence();
            atomicExch(&g_flag[bid], fagg);
        }
        Pose excE = pidentity(), excG = pidentity();
        if (chunk > 0) {
            Pose accE = pidentity(), accG = pidentity();
            bool have = false;
            int base = batch * CHUNKS;
            for (int i = bid - 1; i >= base; --i) {
                int f;
                volatile int* vf = g_flag;
                while ((f = vf[i]) < fagg) { __nanosleep(20); }
                __threadfence();
                Pose pE, pG;
                if (f == fpre) {
                    pair_load_g(g_pre[i], pE, pG);
                    excE = pcompose(pE, accE);
                    excG = pcompose(pG, accG);
                    have = true;
                    break;
                } else {
                    pair_load_g(g_agg[i], pE, pG);
                    accE = pcompose(pE, accE);
                    accG = pcompose(pG, accG);
                }
            }
            if (!have) { excE = accE; excG = accG; }
            pnormq(excE); pnormq(excG);
        }
        if (chunk < CHUNKS - 1) {
            Pose pE = pcompose(excE, aE), pG = pcompose(excG, aG);
            pnormq(pE); pnormq(pG);
            pair_store_g(g_pre[bid], pE, pG);
            __threadfence();
            atomicExch(&g_flag[bid], fpre);
        }
        pstore_s(sexc[0], excE);
        pstore_s(sexc[1], excG);
    }
    __syncthreads();

    // ---- apply prefixes, trajectory losses (4 elems) ----
    Pose baseE = pload_s(sexc[0]);
    Pose baseG = pload_s(sexc[1]);
    if (wid > 0) {
        baseE = pcompose(baseE, pload_s(sw[0][wid - 1]));
        baseG = pcompose(baseG, pload_s(sw[1][wid - 1]));
    }
    // thread-exclusive base via shfl of the (still live) warp-inclusive registers
    Pose LEe = pshfl_up(IE, 1), LEg = pshfl_up(IG, 1);
    Pose preE = (lane == 0) ? baseE : pcompose(baseE, LEe);
    Pose preG = (lane == 0) ? baseG : pcompose(baseG, LEg);

    acc[3] = 0.f; acc[4] = 0.f; acc[5] = 0.f;
#pragma unroll
    for (int i = 0; i < EPT; i++) {
        Pose CE, CG;
        if (i < EPT - 1) {
            CE = pcompose(preE, pload_s(&sP[tid][i * 7]));
            CG = pcompose(preG, pload_s(&sP[tid][21 + i * 7]));
        } else {
            CE = pcompose(baseE, IE);   // cumulative at thread's last element
            CG = pcompose(baseG, IG);
        }
#pragma unroll
        for (int k = 0; k < 3; k++) {
            float d = (&CE.tx)[k] - (&CG.tx)[k];
            acc[3] = fmaf(d, d, acc[3]);
            acc[4] += fabsf(d);
        }
        acc[5] += rot_angle(CE, CG);
    }
    block_reduce6_atomic(acc);
    __syncthreads();

    // ---- last block finalizes ----
    if (tid == 0) {
        __threadfence();
        int old = atomicAdd(&g_done, 1);
        if (old == NBLOCKS - 1) {
            __threadfence();
            const double n3 = (double)NELEM * 3.0, n1 = (double)NELEM;
            double odom = g_accum[2] / n1 + (g_accum[0] / n3 + g_accum[1] / n3);
            double traj = g_accum[5] / n1 + (g_accum[3] / n3 + g_accum[4] / n3);
            out[0] = (float)(0.5 * odom + 0.5 * traj);
#pragma unroll
            for (int j = 0; j < 6; j++) g_accum[j] = 0.0;
            g_done = 0;
            __threadfence();
            g_gen = *(volatile int*)&g_gen + 1;
        }
    }
}

extern "C" void kernel_launch(void* const* d_in, const int* in_sizes, int n_in,
                              void* d_out, int out_size) {
    const float* yhat = (const float*)d_in[0];
    const float* gpos = (const float*)d_in[1];
    const float* gori = (const float*)d_in[2];
    k_main<<<NBLOCKS, NTHREADS>>>(yhat, gpos, gori, (float*)d_out);
}

// round 8
// speedup vs baseline: 2.6559x; 1.0077x over previous
#include <cuda_runtime.h>
#include <math.h>

#define NB 64
#define NS 4096
#define CHUNKS 8
#define CHUNK 512
#define NTHREADS 256
#define HALF 128
#define NWARPS 8
#define EPT 4
#define NBLOCKS (NB * CHUNKS)
#define NELEM (NB * NS)
#define EPSF 1e-6f
#define FULLMASK 0xffffffffu

// Pose = quaternion (w,x,y,z) + translation.
struct Pose { float qw, qx, qy, qz, tx, ty, tz; };

__device__ float  g_agg2[2][NBLOCKS][8];   // per-stream chunk aggregates (0=E, 1=G)
__device__ float  g_pre2[2][NBLOCKS][8];   // per-stream chunk inclusive prefixes
__device__ int    g_flag2[2][NBLOCKS];     // gen-coded: 2*gen = agg ready, 2*gen+1 = prefix ready
__device__ double g_accum[6];              // sq_pos, ab_pos, odom_ang, sq_traj, ab_traj, traj_ang
__device__ int    g_gen = 1;
__device__ int    g_done = 0;

__device__ __forceinline__ Pose pidentity() { return Pose{1.f, 0.f, 0.f, 0.f, 0.f, 0.f, 0.f}; }

// C = A then B (matches einsum x@y order): q = qa*qb, t = ta + rot(qa, tb)
__device__ __forceinline__ Pose pcompose(const Pose& A, const Pose& B) {
    Pose C;
    C.qw = A.qw*B.qw - A.qx*B.qx - A.qy*B.qy - A.qz*B.qz;
    C.qx = A.qw*B.qx + A.qx*B.qw + A.qy*B.qz - A.qz*B.qy;
    C.qy = A.qw*B.qy - A.qx*B.qz + A.qy*B.qw + A.qz*B.qx;
    C.qz = A.qw*B.qz + A.qx*B.qy - A.qy*B.qx + A.qz*B.qw;
    float t2x = 2.f * (A.qy*B.tz - A.qz*B.ty);
    float t2y = 2.f * (A.qz*B.tx - A.qx*B.tz);
    float t2z = 2.f * (A.qx*B.ty - A.qy*B.tx);
    C.tx = A.tx + B.tx + A.qw*t2x + (A.qy*t2z - A.qz*t2y);
    C.ty = A.ty + B.ty + A.qw*t2y + (A.qz*t2x - A.qx*t2z);
    C.tz = A.tz + B.tz + A.qw*t2z + (A.qx*t2y - A.qy*t2x);
    return C;
}

__device__ __forceinline__ void pnormq(Pose& p) {
    float s = rsqrtf(p.qw*p.qw + p.qx*p.qx + p.qy*p.qy + p.qz*p.qz);
    p.qw *= s; p.qx *= s; p.qy *= s; p.qz *= s;
}

__device__ __forceinline__ Pose pshfl_up(const Pose& p, int off) {
    Pose r;
    r.qw = __shfl_up_sync(FULLMASK, p.qw, off);
    r.qx = __shfl_up_sync(FULLMASK, p.qx, off);
    r.qy = __shfl_up_sync(FULLMASK, p.qy, off);
    r.qz = __shfl_up_sync(FULLMASK, p.qz, off);
    r.tx = __shfl_up_sync(FULLMASK, p.tx, off);
    r.ty = __shfl_up_sync(FULLMASK, p.ty, off);
    r.tz = __shfl_up_sync(FULLMASK, p.tz, off);
    return r;
}

// Quaternion for R = Rz(c) @ Ry(b) @ Rx(a). Fast trig is safe: the angle
// formula is norm-invariant and published prefixes are renormalized.
__device__ __forceinline__ void euler_to_quat(float a, float b, float c, Pose& P) {
    float sa, ca, sb, cb, sc, cc;
    __sincosf(0.5f * a, &sa, &ca);
    __sincosf(0.5f * b, &sb, &cb);
    __sincosf(0.5f * c, &sc, &cc);
    P.qw = cc*cb*ca + sc*sb*sa;
    P.qx = cc*cb*sa - sc*sb*ca;
    P.qy = cc*sb*ca + sc*cb*sa;
    P.qz = sc*cb*ca - cc*sb*sa;
}

// arccos((trace(R1 R2^T)-1)/2); for non-unit quats: cos = 2*dot^2/(n1*n2) - 1.
__device__ __forceinline__ float rot_angle(const Pose& A, const Pose& B) {
    float d  = A.qw*B.qw + A.qx*B.qx + A.qy*B.qy + A.qz*B.qz;
    float n1 = A.qw*A.qw + A.qx*A.qx + A.qy*A.qy + A.qz*A.qz;
    float n2 = B.qw*B.qw + B.qx*B.qx + B.qy*B.qy + B.qz*B.qz;
    float c = 2.f * d * d / (n1 * n2) - 1.f;
    c = fminf(fmaxf(c, -1.f + EPSF), 1.f - EPSF);
    return acosf(c);
}

__device__ __forceinline__ void pstore_s(float* p, const Pose& x) {
    p[0]=x.qw; p[1]=x.qx; p[2]=x.qy; p[3]=x.qz; p[4]=x.tx; p[5]=x.ty; p[6]=x.tz;
}
__device__ __forceinline__ Pose pload_s(const float* p) {
    Pose x;
    x.qw=p[0]; x.qx=p[1]; x.qy=p[2]; x.qz=p[3]; x.tx=p[4]; x.ty=p[5]; x.tz=p[6];
    return x;
}
__device__ __forceinline__ void pstore_g8(float* p, const Pose& x) {
    *(float4*)(p)     = make_float4(x.qw, x.qx, x.qy, x.qz);
    *(float4*)(p + 4) = make_float4(x.tx, x.ty, x.tz, 0.f);
}
__device__ __forceinline__ Pose pload_g8(const float* p) {
    float4 a = *(const float4*)(p), b = *(const float4*)(p + 4);
    Pose x;
    x.qw=a.x; x.qx=a.y; x.qy=a.z; x.qz=a.w; x.tx=b.x; x.ty=b.y; x.tz=b.z;
    return x;
}

__device__ __forceinline__ void block_reduce6_atomic(float v[6]) {
#pragma unroll
    for (int o = 16; o > 0; o >>= 1)
#pragma unroll
        for (int j = 0; j < 6; j++) v[j] += __shfl_down_sync(FULLMASK, v[j], o);
    __shared__ float w[6][NWARPS];
    int lane = threadIdx.x & 31, wid = threadIdx.x >> 5;
    if (lane == 0)
#pragma unroll
        for (int j = 0; j < 6; j++) w[j][wid] = v[j];
    __syncthreads();
    if (threadIdx.x < 6) {
        double s = 0.0;
#pragma unroll
        for (int i = 0; i < NWARPS; i++) s += (double)w[threadIdx.x][i];
        atomicAdd(&g_accum[threadIdx.x], s);
    }
}

// Single fused kernel. Warps 0-3 scan the EST stream, warps 4-7 the GT stream
// (same elements). EPT=4 amortization with 2x the warps of R7.
__global__ void __launch_bounds__(NTHREADS) k_main(
    const float* __restrict__ yhat, const float* __restrict__ gpos,
    const float* __restrict__ gori, float* __restrict__ out) {
    __shared__ float sRaw[NTHREADS][29];  // 4 raw poses (28f); later reused for cumulatives
    __shared__ float sPre[NTHREADS][15];  // thread-serial prefixes P1, P2 (14f)
    __shared__ float sw[NWARPS][8];       // warp-inclusive partials (E: 0-3, G: 4-7)
    __shared__ float sexc[2][8];          // chunk-exclusive bases (E, G)

    int tid = threadIdx.x, lane = tid & 31, wid = tid >> 5;
    bool isE = tid < HALF;
    int t = tid & (HALF - 1);
    int bid = blockIdx.x;
    int batch = bid >> 3, chunk = bid & (CHUNKS - 1);
    int s0 = chunk * CHUNK + t * EPT;
    int idx0 = batch * NS + s0;
    int sstream = isE ? 0 : 1;

    // ---- S0: load inputs, build 4 raw poses, serial compose ----
    float ea[4][3], et[4][3];
    if (isE) {
        const float4* y4 = (const float4*)(yhat + (size_t)idx0 * 6);
        float4 y0 = y4[0], y1 = y4[1], y2 = y4[2], y3 = y4[3], y4v = y4[4], y5 = y4[5];
        ea[0][0]=y0.x;  ea[0][1]=y0.y;  ea[0][2]=y0.z;
        et[0][0]=y0.w;  et[0][1]=y1.x;  et[0][2]=y1.y;
        ea[1][0]=y1.z;  ea[1][1]=y1.w;  ea[1][2]=y2.x;
        et[1][0]=y2.y;  et[1][1]=y2.z;  et[1][2]=y2.w;
        ea[2][0]=y3.x;  ea[2][1]=y3.y;  ea[2][2]=y3.z;
        et[2][0]=y3.w;  et[2][1]=y4v.x; et[2][2]=y4v.y;
        ea[3][0]=y4v.z; ea[3][1]=y4v.w; ea[3][2]=y5.x;
        et[3][0]=y5.y;  et[3][1]=y5.z;  et[3][2]=y5.w;
    } else {
        const float4* o4 = (const float4*)(gori + (size_t)idx0 * 3);
        float4 q0 = o4[0], q1 = o4[1], q2 = o4[2];
        const float4* p4 = (const float4*)(gpos + (size_t)idx0 * 3);
        float4 p0 = p4[0], p1 = p4[1], p2 = p4[2];
        ea[0][0]=q0.x; ea[0][1]=q0.y; ea[0][2]=q0.z;
        ea[1][0]=q0.w; ea[1][1]=q1.x; ea[1][2]=q1.y;
        ea[2][0]=q1.z; ea[2][1]=q1.w; ea[2][2]=q2.x;
        ea[3][0]=q2.y; ea[3][1]=q2.z; ea[3][2]=q2.w;
        et[0][0]=p0.x; et[0][1]=p0.y; et[0][2]=p0.z;
        et[1][0]=p0.w; et[1][1]=p1.x; et[1][2]=p1.y;
        et[2][0]=p1.z; et[2][1]=p1.w; et[2][2]=p2.x;
        et[3][0]=p2.y; et[3][1]=p2.z; et[3][2]=p2.w;
    }

    Pose I;
#pragma unroll
    for (int i = 0; i < EPT; i++) {
        Pose P;
        euler_to_quat(ea[i][0], ea[i][1], ea[i][2], P);
        P.tx = et[i][0]; P.ty = et[i][1]; P.tz = et[i][2];
        pstore_s(&sRaw[tid][i * 7], P);                 // raw pose (pre identity-sub)
        if (s0 == 0 && i == 0) P = pidentity();         // shifted[...,0] = I
        if (i == 0) I = P;
        else        I = pcompose(I, P);
        if (i == 1 || i == 2) pstore_s(&sPre[tid][(i - 1) * 7], I);
    }

    // ---- warp-level inclusive scan over thread aggregates (single stream) ----
#pragma unroll
    for (int off = 1; off < 32; off <<= 1) {
        Pose le = pshfl_up(I, off);
        if (lane >= off) I = pcompose(le, I);
    }
    if (lane == 31) pstore_s(sw[wid], I);
    __syncthreads();   // SYNC1: raw poses + warp partials visible

    // ---- S1: cross-warp scans (warp 0: E, warp 4: G), E threads do odometry ----
    if (wid == 0 || wid == 4) {
        int b4 = (wid == 0) ? 0 : 4;
        Pose tI = (lane < 4) ? pload_s(sw[b4 + lane]) : pidentity();
#pragma unroll
        for (int off = 1; off < 4; off <<= 1) {
            Pose le = pshfl_up(tI, off);
            if (lane >= off && lane < 4) tI = pcompose(le, tI);
        }
        if (lane < 4) pstore_s(sw[b4 + lane], tI);
    }

    float acc[6] = {0.f, 0.f, 0.f, 0.f, 0.f, 0.f};
    if (isE) {   // odometry terms: raw E (own stash) vs raw G (partner stash)
#pragma unroll
        for (int i = 0; i < EPT; i++) {
            Pose Er = pload_s(&sRaw[tid][i * 7]);
            Pose Gr = pload_s(&sRaw[tid + HALF][i * 7]);
#pragma unroll
            for (int k = 0; k < 3; k++) {
                float d = (&Er.tx)[k] - (&Gr.tx)[k];
                acc[0] = fmaf(d, d, acc[0]);
                acc[1] += fabsf(d);
            }
            acc[2] += rot_angle(Er, Gr);
        }
    }
    __syncthreads();   // SYNC2: cross-warp partials final

    // ---- S2: two parallel lookback walkers (tid 0 = E, tid 128 = G) ----
    if (tid == 0 || tid == HALF) {
        int gen = *(volatile int*)&g_gen;
        int fagg = 2 * gen, fpre = 2 * gen + 1;
        Pose a = pload_s(sw[sstream ? 7 : 3]);
        pnormq(a);    // cap norm drift at chunk length
        if (chunk < CHUNKS - 1) {
            pstore_g8(g_agg2[sstream][bid], a);
            __threadfence();
            atomicExch(&g_flag2[sstream][bid], fagg);
        }
        Pose exc = pidentity();
        if (chunk > 0) {
            Pose accP = pidentity();
            bool have = false;
            int base = batch * CHUNKS;
            for (int i = bid - 1; i >= base; --i) {
                int f;
                volatile int* vf = g_flag2[sstream];
                while ((f = vf[i]) < fagg) { __nanosleep(20); }
                __threadfence();
                if (f == fpre) {
                    exc = pcompose(pload_g8(g_pre2[sstream][i]), accP);
                    have = true;
                    break;
                } else {
                    accP = pcompose(pload_g8(g_agg2[sstream][i]), accP);
                }
            }
            if (!have) exc = accP;
            pnormq(exc);
        }
        if (chunk < CHUNKS - 1) {
            Pose pr = pcompose(exc, a);
            pnormq(pr);
            pstore_g8(g_pre2[sstream][bid], pr);
            __threadfence();
            atomicExch(&g_flag2[sstream][bid], fpre);
        }
        pstore_s(sexc[sstream], exc);
    }
    __syncthreads();   // SYNC3: sexc visible; all odom reads of raw G done

    // ---- S3: apply prefixes -> 4 cumulative poses, overwrite own sRaw ----
    {
        Pose base = pload_s(sexc[sstream]);
        bool firstw = (wid == (isE ? 0 : 4));
        if (!firstw) base = pcompose(base, pload_s(sw[wid - 1]));
        Pose LE = pshfl_up(I, 1);
        Pose pre = (lane == 0) ? base : pcompose(base, LE);

        Pose P0 = (s0 == 0) ? pidentity() : pload_s(&sRaw[tid][0]);
        Pose C0 = pcompose(pre, P0);
        Pose C1 = pcompose(pre, pload_s(&sPre[tid][0]));
        Pose C2 = pcompose(pre, pload_s(&sPre[tid][7]));
        Pose C3 = pcompose(base, I);
        pstore_s(&sRaw[tid][0],  C0);
        pstore_s(&sRaw[tid][7],  C1);
        pstore_s(&sRaw[tid][14], C2);
        pstore_s(&sRaw[tid][21], C3);
    }
    __syncthreads();   // SYNC4: cumulatives visible

    // ---- S4: G threads compute trajectory terms ----
    if (!isE) {
#pragma unroll
        for (int i = 0; i < EPT; i++) {
            Pose CE = pload_s(&sRaw[tid - HALF][i * 7]);
            Pose CG = pload_s(&sRaw[tid][i * 7]);
#pragma unroll
            for (int k = 0; k < 3; k++) {
                float d = (&CE.tx)[k] - (&CG.tx)[k];
                acc[3] = fmaf(d, d, acc[3]);
                acc[4] += fabsf(d);
            }
            acc[5] += rot_angle(CE, CG);
        }
    }
    block_reduce6_atomic(acc);
    __syncthreads();

    // ---- last block finalizes ----
    if (tid == 0) {
        __threadfence();
        int old = atomicAdd(&g_done, 1);
        if (old == NBLOCKS - 1) {
            __threadfence();
            const double n3 = (double)NELEM * 3.0, n1 = (double)NELEM;
            double odom = g_accum[2] / n1 + (g_accum[0] / n3 + g_accum[1] / n3);
            double traj = g_accum[5] / n1 + (g_accum[3] / n3 + g_accum[4] / n3);
            out[0] = (float)(0.5 * odom + 0.5 * traj);
#pragma unroll
            for (int j = 0; j < 6; j++) g_accum[j] = 0.0;
            g_done = 0;
            __threadfence();
            g_gen = *(volatile int*)&g_gen + 1;
        }
    }
}

extern "C" void kernel_launch(void* const* d_in, const int* in_sizes, int n_in,
                              void* d_out, int out_size) {
    const float* yhat = (const float*)d_in[0];
    const float* gpos = (const float*)d_in[1];
    const float* gori = (const float*)d_in[2];
    k_main<<<NBLOCKS, NTHREADS>>>(yhat, gpos, gori, (float*)d_out);
}

// round 9
// speedup vs baseline: 2.6765x; 1.0077x over previous
#include <cuda_runtime.h>
#include <math.h>

#define NB 64
#define NS 4096
#define CHUNKS 4
#define CHUNK 1024
#define NTHREADS 128
#define NWARPS 4
#define EPT 8
#define NBLOCKS (NB * CHUNKS)
#define NELEM (NB * NS)
#define EPSF 1e-6f
#define FULLMASK 0xffffffffu
#define SS_STRIDE 85   // 84 floats used; stride 85 -> lane bank stride 21, coprime w/ 32

// Pose = quaternion (w,x,y,z) + translation.
struct Pose { float qw, qx, qy, qz, tx, ty, tz; };

__device__ float  g_agg[NBLOCKS][16];   // chunk aggregate   (E in [0..6], G in [8..14])
__device__ float  g_pre[NBLOCKS][16];   // chunk inclusive prefix
__device__ int    g_flag[NBLOCKS];      // gen-coded: 2*gen = agg ready, 2*gen+1 = prefix ready
__device__ double g_accum[6];           // sq_pos, ab_pos, odom_ang, sq_traj, ab_traj, traj_ang
__device__ int    g_gen = 1;
__device__ int    g_done = 0;

__device__ __forceinline__ Pose pidentity() { return Pose{1.f, 0.f, 0.f, 0.f, 0.f, 0.f, 0.f}; }

// C = A then B (matches einsum x@y order): q = qa*qb, t = ta + rot(qa, tb)
__device__ __forceinline__ Pose pcompose(const Pose& A, const Pose& B) {
    Pose C;
    C.qw = A.qw*B.qw - A.qx*B.qx - A.qy*B.qy - A.qz*B.qz;
    C.qx = A.qw*B.qx + A.qx*B.qw + A.qy*B.qz - A.qz*B.qy;
    C.qy = A.qw*B.qy - A.qx*B.qz + A.qy*B.qw + A.qz*B.qx;
    C.qz = A.qw*B.qz + A.qx*B.qy - A.qy*B.qx + A.qz*B.qw;
    float t2x = 2.f * (A.qy*B.tz - A.qz*B.ty);
    float t2y = 2.f * (A.qz*B.tx - A.qx*B.tz);
    float t2z = 2.f * (A.qx*B.ty - A.qy*B.tx);
    C.tx = A.tx + B.tx + A.qw*t2x + (A.qy*t2z - A.qz*t2y);
    C.ty = A.ty + B.ty + A.qw*t2y + (A.qz*t2x - A.qx*t2z);
    C.tz = A.tz + B.tz + A.qw*t2z + (A.qx*t2y - A.qy*t2x);
    return C;
}

__device__ __forceinline__ void pnormq(Pose& p) {
    float s = rsqrtf(p.qw*p.qw + p.qx*p.qx + p.qy*p.qy + p.qz*p.qz);
    p.qw *= s; p.qx *= s; p.qy *= s; p.qz *= s;
}

__device__ __forceinline__ Pose pshfl_up(const Pose& p, int off) {
    Pose r;
    r.qw = __shfl_up_sync(FULLMASK, p.qw, off);
    r.qx = __shfl_up_sync(FULLMASK, p.qx, off);
    r.qy = __shfl_up_sync(FULLMASK, p.qy, off);
    r.qz = __shfl_up_sync(FULLMASK, p.qz, off);
    r.tx = __shfl_up_sync(FULLMASK, p.tx, off);
    r.ty = __shfl_up_sync(FULLMASK, p.ty, off);
    r.tz = __shfl_up_sync(FULLMASK, p.tz, off);
    return r;
}

// Quaternion for R = Rz(c) @ Ry(b) @ Rx(a). Fast trig is safe: the angle
// formula is norm-invariant and published prefixes are renormalized.
__device__ __forceinline__ void euler_to_quat(float a, float b, float c, Pose& P) {
    float sa, ca, sb, cb, sc, cc;
    __sincosf(0.5f * a, &sa, &ca);
    __sincosf(0.5f * b, &sb, &cb);
    __sincosf(0.5f * c, &sc, &cc);
    P.qw = cc*cb*ca + sc*sb*sa;
    P.qx = cc*cb*sa - sc*sb*ca;
    P.qy = cc*sb*ca + sc*cb*sa;
    P.qz = sc*cb*ca - cc*sb*sa;
}

// arccos((trace(R1 R2^T)-1)/2); for non-unit quats: cos = 2*dot^2/(n1*n2) - 1.
__device__ __forceinline__ float rot_angle(const Pose& A, const Pose& B) {
    float d  = A.qw*B.qw + A.qx*B.qx + A.qy*B.qy + A.qz*B.qz;
    float n1 = A.qw*A.qw + A.qx*A.qx + A.qy*A.qy + A.qz*A.qz;
    float n2 = B.qw*B.qw + B.qx*B.qx + B.qy*B.qy + B.qz*B.qz;
    float c = fmaf(2.f * d, __fdividef(d, n1 * n2), -1.f);
    c = fminf(fmaxf(c, -1.f + EPSF), 1.f - EPSF);
    return acosf(c);
}

__device__ __forceinline__ void pstore_s(float* p, const Pose& x) {
    p[0]=x.qw; p[1]=x.qx; p[2]=x.qy; p[3]=x.qz; p[4]=x.tx; p[5]=x.ty; p[6]=x.tz;
}
__device__ __forceinline__ Pose pload_s(const float* p) {
    Pose x;
    x.qw=p[0]; x.qx=p[1]; x.qy=p[2]; x.qz=p[3]; x.tx=p[4]; x.ty=p[5]; x.tz=p[6];
    return x;
}
__device__ __forceinline__ void pair_store_g(float* p, const Pose& e, const Pose& g) {
    *(float4*)(p)      = make_float4(e.qw, e.qx, e.qy, e.qz);
    *(float4*)(p + 4)  = make_float4(e.tx, e.ty, e.tz, 0.f);
    *(float4*)(p + 8)  = make_float4(g.qw, g.qx, g.qy, g.qz);
    *(float4*)(p + 12) = make_float4(g.tx, g.ty, g.tz, 0.f);
}
__device__ __forceinline__ void pair_load_g(const float* p, Pose& e, Pose& g) {
    float4 a = *(const float4*)(p),     b = *(const float4*)(p + 4);
    float4 c = *(const float4*)(p + 8), d = *(const float4*)(p + 12);
    e.qw=a.x; e.qx=a.y; e.qy=a.z; e.qz=a.w; e.tx=b.x; e.ty=b.y; e.tz=b.z;
    g.qw=c.x; g.qx=c.y; g.qy=c.z; g.qz=c.w; g.tx=d.x; g.ty=d.y; g.tz=d.z;
}

__device__ __forceinline__ void block_reduce6_atomic(float v[6]) {
#pragma unroll
    for (int o = 16; o > 0; o >>= 1)
#pragma unroll
        for (int j = 0; j < 6; j++) v[j] += __shfl_down_sync(FULLMASK, v[j], o);
    __shared__ float w[6][NWARPS];
    int lane = threadIdx.x & 31, wid = threadIdx.x >> 5;
    if (lane == 0)
#pragma unroll
        for (int j = 0; j < 6; j++) w[j][wid] = v[j];
    __syncthreads();
    if (threadIdx.x < 6) {
        double s = 0.0;
#pragma unroll
        for (int i = 0; i < NWARPS; i++) s += (double)w[threadIdx.x][i];
        atomicAdd(&g_accum[threadIdx.x], s);
    }
}

// Single fused kernel, EPT=8 (two independent 4-element sub-chains per stream
// for ILP) + warp scan + decoupled lookback + losses + last-block finalize.
__global__ void __launch_bounds__(NTHREADS) k_main(
    const float* __restrict__ yhat, const float* __restrict__ gpos,
    const float* __restrict__ gori, float* __restrict__ out) {
    // Sub-chain prefixes: E: A0@0 A1@7 A2@14 B0@21 B1@28 B2@35; G: same +42.
    __shared__ float sS[NTHREADS][SS_STRIDE];
    __shared__ float sw[2][NWARPS][8];
    __shared__ float sexc[2][8];
    int tid = threadIdx.x, lane = tid & 31, wid = tid >> 5;
    int bid = blockIdx.x;
    int batch = bid >> 2, chunk = bid & (CHUNKS - 1);
    int s0 = chunk * CHUNK + tid * EPT;
    int idx0 = batch * NS + s0;

    float acc[6] = {0.f, 0.f, 0.f, 0.f, 0.f, 0.f};
    Pose A3E, A3G;   // inclusive of elems 0..3 (kept in regs)
    Pose IE, IG;     // thread-inclusive of all 8

    // ---- build 8 poses/stream as two 4-element groups (4 chains in flight) ----
#pragma unroll
    for (int g = 0; g < 2; g++) {
        const float4* y4 = (const float4*)(yhat + (size_t)(idx0 + g * 4) * 6);
        float4 y0 = y4[0], y1 = y4[1], y2 = y4[2], y3 = y4[3], y4v = y4[4], y5 = y4[5];
        const float4* o4 = (const float4*)(gori + (size_t)(idx0 + g * 4) * 3);
        float4 q0 = o4[0], q1 = o4[1], q2 = o4[2];
        const float4* p4 = (const float4*)(gpos + (size_t)(idx0 + g * 4) * 3);
        float4 p0 = p4[0], p1 = p4[1], p2 = p4[2];

        float ea[4][3] = {{y0.x,y0.y,y0.z},{y1.z,y1.w,y2.x},{y3.x,y3.y,y3.z},{y4v.z,y4v.w,y5.x}};
        float et[4][3] = {{y0.w,y1.x,y1.y},{y2.y,y2.z,y2.w},{y3.w,y4v.x,y4v.y},{y5.y,y5.z,y5.w}};
        float ga[4][3] = {{q0.x,q0.y,q0.z},{q0.w,q1.x,q1.y},{q1.z,q1.w,q2.x},{q2.y,q2.z,q2.w}};
        float gt[4][3] = {{p0.x,p0.y,p0.z},{p0.w,p1.x,p1.y},{p1.z,p1.w,p2.x},{p2.y,p2.z,p2.w}};

        Pose CE, CG;
#pragma unroll
        for (int i = 0; i < 4; i++) {
            Pose E, G;
            euler_to_quat(ea[i][0], ea[i][1], ea[i][2], E);
            E.tx = et[i][0]; E.ty = et[i][1]; E.tz = et[i][2];
            euler_to_quat(ga[i][0], ga[i][1], ga[i][2], G);
            G.tx = gt[i][0]; G.ty = gt[i][1]; G.tz = gt[i][2];
#pragma unroll
            for (int k = 0; k < 3; k++) {
                float d = (&E.tx)[k] - (&G.tx)[k];
                acc[0] = fmaf(d, d, acc[0]);
                acc[1] += fabsf(d);
            }
            acc[2] += rot_angle(E, G);
            if (s0 == 0 && g == 0 && i == 0) { E = pidentity(); G = pidentity(); }
            if (i == 0) { CE = E; CG = G; }
            else        { CE = pcompose(CE, E); CG = pcompose(CG, G); }
            if (i < 3) {
                pstore_s(&sS[tid][g * 21 + i * 7], CE);
                pstore_s(&sS[tid][42 + g * 21 + i * 7], CG);
            }
        }
        if (g == 0) { A3E = CE; A3G = CG; }
        else        { IE = pcompose(A3E, CE); IG = pcompose(A3G, CG); }
    }

    // ---- warp-level inclusive scan over thread aggregates ----
#pragma unroll
    for (int off = 1; off < 32; off <<= 1) {
        Pose le = pshfl_up(IE, off), lg = pshfl_up(IG, off);
        if (lane >= off) { IE = pcompose(le, IE); IG = pcompose(lg, IG); }
    }
    if (lane == 31) { pstore_s(sw[0][wid], IE); pstore_s(sw[1][wid], IG); }
    __syncthreads();

    // ---- cross-warp scan (warp 0, 4 entries -> 2 steps) ----
    if (wid == 0) {
        Pose te = (lane < NWARPS) ? pload_s(sw[0][lane]) : pidentity();
        Pose tg = (lane < NWARPS) ? pload_s(sw[1][lane]) : pidentity();
#pragma unroll
        for (int off = 1; off < NWARPS; off <<= 1) {
            Pose le = pshfl_up(te, off), lg = pshfl_up(tg, off);
            if (lane >= off && lane < NWARPS) { te = pcompose(le, te); tg = pcompose(lg, tg); }
        }
        if (lane < NWARPS) { pstore_s(sw[0][lane], te); pstore_s(sw[1][lane], tg); }
    }
    __syncthreads();

    // ---- thread 0: publish aggregate, lookback (depth <= 3), publish prefix ----
    if (tid == 0) {
        int gen = *(volatile int*)&g_gen;
        int fagg = 2 * gen, fpre = 2 * gen + 1;
        Pose aE = pload_s(sw[0][NWARPS - 1]);
        Pose aG = pload_s(sw[1][NWARPS - 1]);
        pnormq(aE); pnormq(aG);   // cap norm drift at chunk length
        if (chunk < CHUNKS - 1) {
            pair_store_g(g_agg[bid], aE, aG);
            __threadfence();
            atomicExch(&g_flag[bid], fagg);
        }
        Pose excE = pidentity(), excG = pidentity();
        if (chunk > 0) {
            Pose accE = pidentity(), accG = pidentity();
            bool have = false;
            int base = batch * CHUNKS;
            for (int i = bid - 1; i >= base; --i) {
                int f;
                volatile int* vf = g_flag;
                while ((f = vf[i]) < fagg) { __nanosleep(20); }
                __threadfence();
                Pose pE, pG;
                if (f == fpre) {
                    pair_load_g(g_pre[i], pE, pG);
                    excE = pcompose(pE, accE);
                    excG = pcompose(pG, accG);
                    have = true;
                    break;
                } else {
                    pair_load_g(g_agg[i], pE, pG);
                    accE = pcompose(pE, accE);
                    accG = pcompose(pG, accG);
                }
            }
            if (!have) { excE = accE; excG = accG; }
            pnormq(excE); pnormq(excG);
        }
        if (chunk < CHUNKS - 1) {
            Pose pE = pcompose(excE, aE), pG = pcompose(excG, aG);
            pnormq(pE); pnormq(pG);
            pair_store_g(g_pre[bid], pE, pG);
            __threadfence();
            atomicExch(&g_flag[bid], fpre);
        }
        pstore_s(sexc[0], excE);
        pstore_s(sexc[1], excG);
    }
    __syncthreads();

    // ---- apply prefixes, trajectory losses (8 elems) ----
    Pose baseE = pload_s(sexc[0]);
    Pose baseG = pload_s(sexc[1]);
    if (wid > 0) {
        baseE = pcompose(baseE, pload_s(sw[0][wid - 1]));
        baseG = pcompose(baseG, pload_s(sw[1][wid - 1]));
    }
    // thread-exclusive base via shfl of the (still live) warp-inclusive registers
    Pose LEe = pshfl_up(IE, 1), LEg = pshfl_up(IG, 1);
    Pose preE = (lane == 0) ? baseE : pcompose(baseE, LEe);
    Pose preG = (lane == 0) ? baseG : pcompose(baseG, LEg);

    Pose preBE = pcompose(preE, A3E);   // cumulative at elem 3 (= C3)
    Pose preBG = pcompose(preG, A3G);

#pragma unroll
    for (int i = 0; i < EPT; i++) {
        Pose CE, CG;
        if (i < 3) {
            CE = pcompose(preE, pload_s(&sS[tid][i * 7]));
            CG = pcompose(preG, pload_s(&sS[tid][42 + i * 7]));
        } else if (i == 3) {
            CE = preBE; CG = preBG;
        } else if (i < 7) {
            CE = pcompose(preBE, pload_s(&sS[tid][21 + (i - 4) * 7]));
            CG = pcompose(preBG, pload_s(&sS[tid][63 + (i - 4) * 7]));
        } else {
            CE = pcompose(baseE, IE);
            CG = pcompose(baseG, IG);
        }
#pragma unroll
        for (int k = 0; k < 3; k++) {
            float d = (&CE.tx)[k] - (&CG.tx)[k];
            acc[3] = fmaf(d, d, acc[3]);
            acc[4] += fabsf(d);
        }
        acc[5] += rot_angle(CE, CG);
    }
    block_reduce6_atomic(acc);
    __syncthreads();

    // ---- last block finalizes ----
    if (tid == 0) {
        __threadfence();
        int old = atomicAdd(&g_done, 1);
        if (old == NBLOCKS - 1) {
            __threadfence();
            const double n3 = (double)NELEM * 3.0, n1 = (double)NELEM;
            double odom = g_accum[2] / n1 + (g_accum[0] / n3 + g_accum[1] / n3);
            double traj = g_accum[5] / n1 + (g_accum[3] / n3 + g_accum[4] / n3);
            out[0] = (float)(0.5 * odom + 0.5 * traj);
#pragma unroll
            for (int j = 0; j < 6; j++) g_accum[j] = 0.0;
            g_done = 0;
            __threadfence();
            g_gen = *(volatile int*)&g_gen + 1;
        }
    }
}

extern "C" void kernel_launch(void* const* d_in, const int* in_sizes, int n_in,
                              void* d_out, int out_size) {
    const float* yhat = (const float*)d_in[0];
    const float* gpos = (const float*)d_in[1];
    const float* gori = (const float*)d_in[2];
    k_main<<<NBLOCKS, NTHREADS>>>(yhat, gpos, gori, (float*)d_out);
}